// round 7
// baseline (speedup 1.0000x reference)
#include <cuda_runtime.h>
#include <cuda_bf16.h>
#include <cstdint>

// ---------------------------------------------------------------------------
// CrossAttention on GB300 (sm_103a; plain compute_103 target -> mma.sync bf16).
// All GEMMs use m16n8k16 bf16 3-term hi/lo split (AhBh+AhBl+AlBh, fp32 acc).
// R7: all operands pre-converted to bf16 hi/lo at their producer; hot loops
// stage via cp.async (2-stage double buffer, zfill halo), no in-loop cvt.
// ---------------------------------------------------------------------------

#define NB   4
#define CCH  512
#define HW   1024
#define NHD  8
#define DHEAD 128

typedef __nv_bfloat16 bf16;

// Scratch (no allocations -> __device__ globals)
__device__ bf16  g_wh[6][9 * 512 * 512], g_wl[6][9 * 512 * 512];   // [r][co][ci]
__device__ bf16  g_xh[2][NB * HW * CCH], g_xl[2][NB * HW * CCH];   // [n][hw][ci]
__device__ bf16  g_qh[6][NB * CCH * HW], g_ql[6][NB * CCH * HW];   // qkv h/l
__device__ float g_att[2][NB * NHD * 512 * 512];                   // pre-softmax
__device__ bf16  g_ah[2][NB * NHD * 512 * 512], g_al[2][NB * NHD * 512 * 512];
__device__ bf16  g_yh[2][NB * CCH * HW], g_yl[2][NB * CCH * HW];
__device__ bf16  g_wph[2][512 * 512], g_wpl[2][512 * 512];

// ============================ helpers =======================================
__device__ __forceinline__ uint32_t smem_u32(const void* p) {
    uint32_t a;
    asm("{ .reg .u64 t; cvta.to.shared.u64 t, %1; cvt.u32.u64 %0, t; }"
        : "=r"(a) : "l"(p));
    return a;
}

__device__ __forceinline__ void mma_bf16(float* c, const uint32_t* a, const uint32_t* b) {
    asm volatile(
        "mma.sync.aligned.m16n8k16.row.col.f32.bf16.bf16.f32 "
        "{%0,%1,%2,%3}, {%4,%5,%6,%7}, {%8,%9}, {%0,%1,%2,%3};"
        : "+f"(c[0]), "+f"(c[1]), "+f"(c[2]), "+f"(c[3])
        : "r"(a[0]), "r"(a[1]), "r"(a[2]), "r"(a[3]), "r"(b[0]), "r"(b[1]));
}

#define LDSM4(r0, r1, r2, r3, addr) \
    asm volatile("ldmatrix.sync.aligned.m8n8.x4.shared.b16 {%0,%1,%2,%3}, [%4];" \
                 : "=r"(r0), "=r"(r1), "=r"(r2), "=r"(r3) : "r"(addr))

#define LDSM2T(r0, r1, addr) \
    asm volatile("ldmatrix.sync.aligned.m8n8.x2.trans.shared.b16 {%0,%1}, [%2];" \
                 : "=r"(r0), "=r"(r1) : "r"(addr))

#define CPA(dst, src, sz) \
    asm volatile("cp.async.cg.shared.global [%0], [%1], 16, %2;" \
                 :: "r"(dst), "l"(src), "r"(sz) : "memory")
#define CP_COMMIT() asm volatile("cp.async.commit_group;" ::: "memory")
#define CP_WAIT1()  asm volatile("cp.async.wait_group 1;" ::: "memory")
#define CP_WAIT0()  asm volatile("cp.async.wait_group 0;" ::: "memory")

// fp32 pair -> bf16x2 hi + lo words
__device__ __forceinline__ void pair_hilo(float a, float b, uint32_t& h, uint32_t& l) {
    __nv_bfloat162 hh = __floats2bfloat162_rn(a, b);
    float2 f = __bfloat1622float2(hh);
    __nv_bfloat162 ll = __floats2bfloat162_rn(a - f.x, b - f.y);
    h = *(uint32_t*)&hh; l = *(uint32_t*)&ll;
}
__device__ __forceinline__ void scalar_hilo(float v, bf16& h, bf16& l) {
    h = __float2bfloat16_rn(v);
    l = __float2bfloat16_rn(v - __bfloat162float(h));
}

// ============================ prep kernels ==================================
// w [co][ci][3][3] -> [conv][r][co][ci] bf16 hi/lo
__global__ void prep_w3(const float* __restrict__ w0, const float* __restrict__ w1,
                        const float* __restrict__ w2, const float* __restrict__ w3,
                        const float* __restrict__ w4, const float* __restrict__ w5,
                        bf16* __restrict__ wh, bf16* __restrict__ wl) {
    const float* ws[6] = {w0, w1, w2, w3, w4, w5};
    int conv = blockIdx.y;
    const float* w = ws[conv];
    int t = blockIdx.x * 256 + threadIdx.x;
    int co = t >> 9, ci = t & 511;
    float v[9];
#pragma unroll
    for (int r = 0; r < 9; ++r) v[r] = w[(size_t)t * 9 + r];
#pragma unroll
    for (int r = 0; r < 9; ++r) {
        size_t o = (((size_t)conv * 9 + r) * 512 + co) * 512 + ci;
        bf16 h, l; scalar_hilo(v[r], h, l);
        wh[o] = h; wl[o] = l;
    }
}
// Wp [co][ci] fp32 -> bf16 hi/lo (no transpose; A path is row-major co,ci)
__global__ void prep_wp(const float* __restrict__ wp1, const float* __restrict__ wp2,
                        bf16* __restrict__ wh, bf16* __restrict__ wl) {
    int pidx = blockIdx.y;
    const float* w = pidx ? wp2 : wp1;
    int idx = blockIdx.x * 256 + threadIdx.x;
    bf16 h, l; scalar_hilo(w[idx], h, l);
    size_t o = (size_t)pidx * 512 * 512 + idx;
    wh[o] = h; wl[o] = l;
}
// x [n][c][hw] -> xt [n][hw][c] bf16 hi/lo
__global__ void transpose_x(const float* __restrict__ xl, const float* __restrict__ xg,
                            bf16* __restrict__ xth, bf16* __restrict__ xtl) {
    __shared__ float tile[32][33];
    int zt = blockIdx.z, tsel = zt >> 2, n = zt & 3;
    const float* x = (tsel ? xg : xl) + (size_t)n * (CCH * HW);
    size_t ob = (size_t)tsel * NB * HW * CCH + (size_t)n * (HW * CCH);
    int hw0 = blockIdx.x * 32, c0 = blockIdx.y * 32;
    int tx = threadIdx.x, ty = threadIdx.y;
#pragma unroll
    for (int i = 0; i < 32; i += 8)
        tile[ty + i][tx] = x[(size_t)(c0 + ty + i) * HW + hw0 + tx];
    __syncthreads();
#pragma unroll
    for (int i = 0; i < 32; i += 8) {
        float v = tile[tx][ty + i];
        bf16 h, l; scalar_hilo(v, h, l);
        size_t o = ob + (size_t)(hw0 + ty + i) * CCH + c0 + tx;
        xth[o] = h; xtl[o] = l;
    }
}

// ============================ layout consts =================================
#define ROWB 80                   // 32 bf16 (64B) + 16B pad
#define MATB (128 * ROWB)         // 10240
#define ROW2 272                  // 128 bf16 (256B) + 16B pad
#define MATB2 (32 * ROW2)         // 8704
#define STG4 (4 * MATB)           // conv/qk stage: Ah Al Bh Bl        40960
#define SM4  (2 * STG4)           // 81920
#define STGT (2 * MATB + 2 * MATB2) // av/proj stage                  37888
#define SMT  (2 * STGT)           // 75776

// ======================= shared mma inner phase =============================
__device__ __forceinline__ void mma_phase_nn(uint32_t sAh, uint32_t sAl,
                                             uint32_t sBh, uint32_t sBl,
                                             uint32_t a_base, uint32_t b_base,
                                             float acc[4][4][4]) {
#pragma unroll
    for (int kt = 0; kt < 2; ++kt) {
        uint32_t aH[4][4], aL[4][4], bH[4][2], bL[4][2];
#pragma unroll
        for (int mt = 0; mt < 4; ++mt) {
            uint32_t ad = a_base + (uint32_t)(mt * 16 * ROWB + kt * 32);
            LDSM4(aH[mt][0], aH[mt][1], aH[mt][2], aH[mt][3], sAh + ad);
            LDSM4(aL[mt][0], aL[mt][1], aL[mt][2], aL[mt][3], sAl + ad);
        }
#pragma unroll
        for (int p = 0; p < 2; ++p) {
            uint32_t bd = b_base + (uint32_t)(p * 16 * ROWB + kt * 32);
            uint32_t r0, r1, r2, r3;
            LDSM4(r0, r1, r2, r3, sBh + bd);
            bH[2 * p][0] = r0; bH[2 * p][1] = r2;
            bH[2 * p + 1][0] = r1; bH[2 * p + 1][1] = r3;
            LDSM4(r0, r1, r2, r3, sBl + bd);
            bL[2 * p][0] = r0; bL[2 * p][1] = r2;
            bL[2 * p + 1][0] = r1; bL[2 * p + 1][1] = r3;
        }
#pragma unroll
        for (int mt = 0; mt < 4; ++mt)
#pragma unroll
            for (int nt = 0; nt < 4; ++nt) {
                mma_bf16(acc[mt][nt], aH[mt], bH[nt]);
                mma_bf16(acc[mt][nt], aH[mt], bL[nt]);
                mma_bf16(acc[mt][nt], aL[mt], bH[nt]);
            }
    }
}

__device__ __forceinline__ void mma_phase_nt(uint32_t sAh, uint32_t sAl,
                                             uint32_t sBh, uint32_t sBl,
                                             uint32_t a_base, uint32_t bt_base,
                                             float acc[4][4][4]) {
#pragma unroll
    for (int kt = 0; kt < 2; ++kt) {
        uint32_t aH[4][4], aL[4][4], bH[4][2], bL[4][2];
#pragma unroll
        for (int mt = 0; mt < 4; ++mt) {
            uint32_t ad = a_base + (uint32_t)(mt * 16 * ROWB + kt * 32);
            LDSM4(aH[mt][0], aH[mt][1], aH[mt][2], aH[mt][3], sAh + ad);
            LDSM4(aL[mt][0], aL[mt][1], aL[mt][2], aL[mt][3], sAl + ad);
        }
#pragma unroll
        for (int nt = 0; nt < 4; ++nt) {
            uint32_t bd = bt_base + (uint32_t)(kt * 16 * ROW2 + nt * 16);
            LDSM2T(bH[nt][0], bH[nt][1], sBh + bd);
            LDSM2T(bL[nt][0], bL[nt][1], sBl + bd);
        }
#pragma unroll
        for (int mt = 0; mt < 4; ++mt)
#pragma unroll
            for (int nt = 0; nt < 4; ++nt) {
                mma_bf16(acc[mt][nt], aH[mt], bH[nt]);
                mma_bf16(acc[mt][nt], aH[mt], bL[nt]);
                mma_bf16(acc[mt][nt], aL[mt], bH[nt]);
            }
    }
}

// ================== conv 3x3: cp.async 2-stage + mma ========================
// grid (8 s-tiles, 4 co-tiles, 24 conv*n), 256 threads, 2 CTAs/SM target.
__global__ __launch_bounds__(256, 2)
void conv_mma_kernel(const bf16* __restrict__ xth, const bf16* __restrict__ xtl,
                     const bf16* __restrict__ wh, const bf16* __restrict__ wl,
                     bf16* __restrict__ qh, bf16* __restrict__ ql) {
    extern __shared__ unsigned char dsm[];
    const uint32_t sb = smem_u32(dsm);

    int tid = threadIdx.x, wid = tid >> 5, lid = tid & 31;
    int warp_m = wid >> 2, warp_n = wid & 3;
    int sp0 = blockIdx.x * 128, co0 = blockIdx.y * 128;
    int conv = blockIdx.z >> 2, n = blockIdx.z & 3;
    size_t xoffb = ((size_t)(conv < 3 ? 0 : 1) * NB + n) * (HW * CCH);
    const bf16* xh = xth + xoffb;
    const bf16* xl = xtl + xoffb;
    const bf16* wbh = wh + (size_t)conv * (9 * 512 * 512);
    const bf16* wbl = wl + (size_t)conv * (9 * 512 * 512);
    bf16* oh = qh + ((size_t)conv * NB + n) * (CCH * HW);
    bf16* ol = ql + ((size_t)conv * NB + n) * (CCH * HW);

    float acc[4][4][4];
#pragma unroll
    for (int mt = 0; mt < 4; ++mt)
#pragma unroll
        for (int nt = 0; nt < 4; ++nt)
#pragma unroll
            for (int k = 0; k < 4; ++k) acc[mt][nt][k] = 0.f;

    int grp = lid >> 3, lr = lid & 7;
    uint32_t a_base = (uint32_t)((warp_m * 64 + (grp & 1) * 8 + lr) * ROWB + (grp >> 1) * 16);
    uint32_t b_base = (uint32_t)((warp_n * 32 + (grp & 1) * 8 + lr) * ROWB + (grp >> 1) * 16);

    int row = tid >> 1, half = tid & 1;
    uint32_t dstA = (uint32_t)(row * ROWB + half * 32);

    auto prefetch = [&](int ch, int st) {
        uint32_t s0b = sb + st * STG4;
        int r = ch >> 4, ci0 = (ch & 15) << 5;
        int dy = r / 3 - 1, dx = r % 3 - 1;
        size_t wof = ((size_t)r * 512 + co0 + row) * 512 + ci0 + half * 16;
        uint32_t da = s0b + dstA;
        CPA(da,             wbh + wof,     16u);
        CPA(da + 16,        wbh + wof + 8, 16u);
        CPA(da + MATB,      wbl + wof,     16u);
        CPA(da + MATB + 16, wbl + wof + 8, 16u);
        int s = sp0 + row;
        int yy = (s >> 5) + dy, xx = (s & 31) + dx;
        bool ok = ((unsigned)yy < 32u) && ((unsigned)xx < 32u);
        size_t xof = ok ? ((size_t)(yy * 32 + xx) * 512 + ci0 + half * 16) : 0;
        uint32_t sz = ok ? 16u : 0u;
        uint32_t db = s0b + 2 * MATB + dstA;
        CPA(db,             xh + xof,     sz);
        CPA(db + 16,        xh + xof + 8, sz);
        CPA(db + MATB,      xl + xof,     sz);
        CPA(db + MATB + 16, xl + xof + 8, sz);
    };

    prefetch(0, 0); CP_COMMIT();
    for (int ch = 0; ch < 144; ++ch) {
        if (ch + 1 < 144) { prefetch(ch + 1, (ch + 1) & 1); CP_COMMIT(); CP_WAIT1(); }
        else CP_WAIT0();
        __syncthreads();
        uint32_t st = sb + (ch & 1) * STG4;
        mma_phase_nn(st, st + MATB, st + 2 * MATB, st + 3 * MATB, a_base, b_base, acc);
        __syncthreads();
    }

#pragma unroll
    for (int mt = 0; mt < 4; ++mt) {
        int m = co0 + warp_m * 64 + mt * 16 + (lid >> 2);
#pragma unroll
        for (int nt = 0; nt < 4; ++nt) {
            int sc = sp0 + warp_n * 32 + nt * 8 + (lid & 3) * 2;
            uint32_t h, l;
            pair_hilo(acc[mt][nt][0], acc[mt][nt][1], h, l);
            *(uint32_t*)&oh[(size_t)m * HW + sc] = h;
            *(uint32_t*)&ol[(size_t)m * HW + sc] = l;
            pair_hilo(acc[mt][nt][2], acc[mt][nt][3], h, l);
            *(uint32_t*)&oh[(size_t)(m + 8) * HW + sc] = h;
            *(uint32_t*)&ol[(size_t)(m + 8) * HW + sc] = l;
        }
    }
}

// ======================== QK^T: cp.async + mma ==============================
// grid (4 ck-tiles, 4 cq-tiles, 32 nh)
__global__ __launch_bounds__(256, 2)
void qk_mma_kernel(const bf16* __restrict__ q_h, const bf16* __restrict__ q_l,
                   const bf16* __restrict__ k_h, const bf16* __restrict__ k_l,
                   float* __restrict__ att) {
    extern __shared__ unsigned char dsm[];
    const uint32_t sb = smem_u32(dsm);

    int tid = threadIdx.x, wid = tid >> 5, lid = tid & 31;
    int warp_m = wid >> 2, warp_n = wid & 3;
    int nh = blockIdx.z, n = nh >> 3, h = nh & 7;
    int ck0 = blockIdx.x * 128, cq0 = blockIdx.y * 128;
    size_t qb = (size_t)n * (CCH * HW) + h * DHEAD;
    const bf16* qh = q_h + qb; const bf16* ql = q_l + qb;
    const bf16* kh = k_h + qb; const bf16* kl = k_l + qb;

    float acc[4][4][4];
#pragma unroll
    for (int mt = 0; mt < 4; ++mt)
#pragma unroll
        for (int nt = 0; nt < 4; ++nt)
#pragma unroll
            for (int kk = 0; kk < 4; ++kk) acc[mt][nt][kk] = 0.f;

    int grp = lid >> 3, lr = lid & 7;
    uint32_t a_base = (uint32_t)((warp_m * 64 + (grp & 1) * 8 + lr) * ROWB + (grp >> 1) * 16);
    uint32_t b_base = (uint32_t)((warp_n * 32 + (grp & 1) * 8 + lr) * ROWB + (grp >> 1) * 16);

    int row = tid >> 1, half = tid & 1;
    uint32_t dstA = (uint32_t)(row * ROWB + half * 32);

    auto prefetch = [&](int ch, int st) {
        uint32_t s0b = sb + st * STG4;
        int ci0 = ch << 5;
        size_t qof = (size_t)(cq0 + row) * HW + ci0 + half * 16;
        size_t kof = (size_t)(ck0 + row) * HW + ci0 + half * 16;
        uint32_t da = s0b + dstA;
        CPA(da,             qh + qof,     16u);
        CPA(da + 16,        qh + qof + 8, 16u);
        CPA(da + MATB,      ql + qof,     16u);
        CPA(da + MATB + 16, ql + qof + 8, 16u);
        uint32_t db = s0b + 2 * MATB + dstA;
        CPA(db,             kh + kof,     16u);
        CPA(db + 16,        kh + kof + 8, 16u);
        CPA(db + MATB,      kl + kof,     16u);
        CPA(db + MATB + 16, kl + kof + 8, 16u);
    };

    prefetch(0, 0); CP_COMMIT();
    for (int ch = 0; ch < 4; ++ch) {
        if (ch + 1 < 4) { prefetch(ch + 1, (ch + 1) & 1); CP_COMMIT(); CP_WAIT1(); }
        else CP_WAIT0();
        __syncthreads();
        uint32_t st = sb + (ch & 1) * STG4;
        mma_phase_nn(st, st + MATB, st + 2 * MATB, st + 3 * MATB, a_base, b_base, acc);
        __syncthreads();
    }

    const float SC = 0.08838834764831845f;   // 1/sqrt(128)
    float* ab = att + (size_t)(n * NHD + h) * 512 * 512;
#pragma unroll
    for (int mt = 0; mt < 4; ++mt) {
        int m = cq0 + warp_m * 64 + mt * 16 + (lid >> 2);
#pragma unroll
        for (int nt = 0; nt < 4; ++nt) {
            int sc = ck0 + warp_n * 32 + nt * 8 + (lid & 3) * 2;
            *(float2*)(ab + (size_t)m * 512 + sc) =
                make_float2(acc[mt][nt][0] * SC, acc[mt][nt][1] * SC);
            *(float2*)(ab + (size_t)(m + 8) * 512 + sc) =
                make_float2(acc[mt][nt][2] * SC, acc[mt][nt][3] * SC);
        }
    }
}

// ----------------- softmax: fp32 in -> bf16 hi/lo out -----------------------
__global__ void softmax_kernel(const float* __restrict__ att,
                               bf16* __restrict__ ah, bf16* __restrict__ al) {
    int row  = blockIdx.x * 8 + (threadIdx.x >> 5);
    int lane = threadIdx.x & 31;
    const float* p = att + (size_t)row * 512;
    bf16* ph = ah + (size_t)row * 512;
    bf16* pl = al + (size_t)row * 512;
    float v[16];
    float m = -1e30f;
#pragma unroll
    for (int i = 0; i < 16; ++i) { v[i] = p[lane + i * 32]; m = fmaxf(m, v[i]); }
#pragma unroll
    for (int o = 16; o; o >>= 1) m = fmaxf(m, __shfl_xor_sync(0xffffffffu, m, o));
    float s = 0.f;
#pragma unroll
    for (int i = 0; i < 16; ++i) { v[i] = __expf(v[i] - m); s += v[i]; }
#pragma unroll
    for (int o = 16; o; o >>= 1) s += __shfl_xor_sync(0xffffffffu, s, o);
    float inv = 1.f / s;
#pragma unroll
    for (int i = 0; i < 16; ++i) {
        float val = v[i] * inv;
        bf16 hh, ll; scalar_hilo(val, hh, ll);
        ph[lane + i * 32] = hh;
        pl[lane + i * 32] = ll;
    }
}

// ===================== AV: cp.async + mma (B trans) =========================
// grid (4 cq-tiles, 32 nh)
__global__ __launch_bounds__(256, 2)
void av_mma_kernel(const bf16* __restrict__ a_h, const bf16* __restrict__ a_l,
                   const bf16* __restrict__ v_h, const bf16* __restrict__ v_l,
                   bf16* __restrict__ y_h, bf16* __restrict__ y_l) {
    extern __shared__ unsigned char dsm[];
    const uint32_t sb = smem_u32(dsm);

    int tid = threadIdx.x, wid = tid >> 5, lid = tid & 31;
    int warp_m = wid >> 2, warp_n = wid & 3;
    int nh = blockIdx.y, n = nh >> 3, h = nh & 7;
    int cq0 = blockIdx.x * 128;
    size_t abo = (size_t)(n * NHD + h) * 512 * 512;
    const bf16* ah = a_h + abo; const bf16* al = a_l + abo;
    size_t vbo = (size_t)n * (CCH * HW) + h * DHEAD;
    const bf16* vh = v_h + vbo; const bf16* vl = v_l + vbo;

    float acc[4][4][4];
#pragma unroll
    for (int mt = 0; mt < 4; ++mt)
#pragma unroll
        for (int nt = 0; nt < 4; ++nt)
#pragma unroll
            for (int kk = 0; kk < 4; ++kk) acc[mt][nt][kk] = 0.f;

    int grp = lid >> 3, lr = lid & 7;
    uint32_t a_base = (uint32_t)((warp_m * 64 + (grp & 1) * 8 + lr) * ROWB + (grp >> 1) * 16);
    int l16 = lid & 15;
    uint32_t bt_base = (uint32_t)(l16 * ROW2 + warp_n * 64);

    int row = tid >> 1, half = tid & 1;
    uint32_t dstA = (uint32_t)(row * ROWB + half * 32);
    int ckr = tid >> 3, seg = tid & 7;
    uint32_t dstB = (uint32_t)(ckr * ROW2 + seg * 32);

    auto prefetch = [&](int ch, int st) {
        uint32_t s0b = sb + st * STGT;
        int ci0 = ch << 5;
        size_t aof = (size_t)(cq0 + row) * 512 + ci0 + half * 16;
        uint32_t da = s0b + dstA;
        CPA(da,             ah + aof,     16u);
        CPA(da + 16,        ah + aof + 8, 16u);
        CPA(da + MATB,      al + aof,     16u);
        CPA(da + MATB + 16, al + aof + 8, 16u);
        size_t vof = (size_t)(ci0 + ckr) * HW + seg * 16;
        uint32_t db = s0b + 2 * MATB + dstB;
        CPA(db,              vh + vof,     16u);
        CPA(db + 16,         vh + vof + 8, 16u);
        CPA(db + MATB2,      vl + vof,     16u);
        CPA(db + MATB2 + 16, vl + vof + 8, 16u);
    };

    prefetch(0, 0); CP_COMMIT();
    for (int ch = 0; ch < 16; ++ch) {
        if (ch + 1 < 16) { prefetch(ch + 1, (ch + 1) & 1); CP_COMMIT(); CP_WAIT1(); }
        else CP_WAIT0();
        __syncthreads();
        uint32_t st = sb + (ch & 1) * STGT;
        mma_phase_nt(st, st + MATB, st + 2 * MATB, st + 2 * MATB + MATB2,
                     a_base, bt_base, acc);
        __syncthreads();
    }

    bf16* yh = y_h + vbo;
    bf16* yl = y_l + vbo;
#pragma unroll
    for (int mt = 0; mt < 4; ++mt) {
        int m = cq0 + warp_m * 64 + mt * 16 + (lid >> 2);
#pragma unroll
        for (int nt = 0; nt < 4; ++nt) {
            int dc = warp_n * 32 + nt * 8 + (lid & 3) * 2;
            uint32_t h2, l2;
            pair_hilo(acc[mt][nt][0], acc[mt][nt][1], h2, l2);
            *(uint32_t*)&yh[(size_t)m * HW + dc] = h2;
            *(uint32_t*)&yl[(size_t)m * HW + dc] = l2;
            pair_hilo(acc[mt][nt][2], acc[mt][nt][3], h2, l2);
            *(uint32_t*)&yh[(size_t)(m + 8) * HW + dc] = h2;
            *(uint32_t*)&yl[(size_t)(m + 8) * HW + dc] = l2;
        }
    }
}

// ============ 1x1 proj + residual: cp.async + mma (B trans) =================
// grid (8 s-tiles, 4 co-tiles, 4 n)
__global__ __launch_bounds__(256, 2)
void proj_mma_kernel(const bf16* __restrict__ y_h, const bf16* __restrict__ y_l,
                     const bf16* __restrict__ w_h, const bf16* __restrict__ w_l,
                     const float* __restrict__ xres, const float* __restrict__ rwp,
                     float* __restrict__ out) {
    extern __shared__ unsigned char dsm[];
    const uint32_t sb = smem_u32(dsm);

    int tid = threadIdx.x, wid = tid >> 5, lid = tid & 31;
    int warp_m = wid >> 2, warp_n = wid & 3;
    int sp0 = blockIdx.x * 128, co0 = blockIdx.y * 128, n = blockIdx.z;
    const bf16* yh = y_h + (size_t)n * (CCH * HW);
    const bf16* yl = y_l + (size_t)n * (CCH * HW);

    float acc[4][4][4];
#pragma unroll
    for (int mt = 0; mt < 4; ++mt)
#pragma unroll
        for (int nt = 0; nt < 4; ++nt)
#pragma unroll
            for (int kk = 0; kk < 4; ++kk) acc[mt][nt][kk] = 0.f;

    int grp = lid >> 3, lr = lid & 7;
    uint32_t a_base = (uint32_t)((warp_m * 64 + (grp & 1) * 8 + lr) * ROWB + (grp >> 1) * 16);
    int l16 = lid & 15;
    uint32_t bt_base = (uint32_t)(l16 * ROW2 + warp_n * 64);

    int row = tid >> 1, half = tid & 1;
    uint32_t dstA = (uint32_t)(row * ROWB + half * 32);
    int ckr = tid >> 3, seg = tid & 7;
    uint32_t dstB = (uint32_t)(ckr * ROW2 + seg * 32);

    auto prefetch = [&](int ch, int st) {
        uint32_t s0b = sb + st * STGT;
        int ci0 = ch << 5;
        size_t wof = (size_t)(co0 + row) * 512 + ci0 + half * 16;
        uint32_t da = s0b + dstA;
        CPA(da,             w_h + wof,     16u);
        CPA(da + 16,        w_h + wof + 8, 16u);
        CPA(da + MATB,      w_l + wof,     16u);
        CPA(da + MATB + 16, w_l + wof + 8, 16u);
        size_t yof = (size_t)(ci0 + ckr) * HW + sp0 + seg * 16;
        uint32_t db = s0b + 2 * MATB + dstB;
        CPA(db,              yh + yof,     16u);
        CPA(db + 16,         yh + yof + 8, 16u);
        CPA(db + MATB2,      yl + yof,     16u);
        CPA(db + MATB2 + 16, yl + yof + 8, 16u);
    };

    prefetch(0, 0); CP_COMMIT();
    for (int ch = 0; ch < 16; ++ch) {
        if (ch + 1 < 16) { prefetch(ch + 1, (ch + 1) & 1); CP_COMMIT(); CP_WAIT1(); }
        else CP_WAIT0();
        __syncthreads();
        uint32_t st = sb + (ch & 1) * STGT;
        mma_phase_nt(st, st + MATB, st + 2 * MATB, st + 2 * MATB + MATB2,
                     a_base, bt_base, acc);
        __syncthreads();
    }

    float rw = *rwp;
#pragma unroll
    for (int mt = 0; mt < 4; ++mt) {
        int m = co0 + warp_m * 64 + mt * 16 + (lid >> 2);
#pragma unroll
        for (int nt = 0; nt < 4; ++nt) {
            int sc = sp0 + warp_n * 32 + nt * 8 + (lid & 3) * 2;
            size_t b0 = ((size_t)n * CCH + m) * HW + sc;
            size_t b1 = ((size_t)n * CCH + m + 8) * HW + sc;
            float2 x0 = *(const float2*)(xres + b0);
            float2 x1 = *(const float2*)(xres + b1);
            *(float2*)(out + b0) = make_float2(x0.x + rw * acc[mt][nt][0],
                                               x0.y + rw * acc[mt][nt][1]);
            *(float2*)(out + b1) = make_float2(x1.x + rw * acc[mt][nt][2],
                                               x1.y + rw * acc[mt][nt][3]);
        }
    }
}

// ------------------------------- launcher -----------------------------------
extern "C" void kernel_launch(void* const* d_in, const int* in_sizes, int n_in,
                              void* d_out, int out_size) {
    (void)in_sizes; (void)n_in; (void)out_size;
    const float* x_l = (const float*)d_in[0];
    const float* x_g = (const float*)d_in[1];
    const float* Wp1 = (const float*)d_in[8];
    const float* Wp2 = (const float*)d_in[9];
    const float* rw  = (const float*)d_in[10];
    float* out_l = (float*)d_out;
    float* out_g = out_l + (size_t)NB * CCH * HW;

    void* p;
    cudaGetSymbolAddress(&p, g_wh);  bf16* wh  = (bf16*)p;
    cudaGetSymbolAddress(&p, g_wl);  bf16* wl  = (bf16*)p;
    cudaGetSymbolAddress(&p, g_xh);  bf16* xh  = (bf16*)p;
    cudaGetSymbolAddress(&p, g_xl);  bf16* xl  = (bf16*)p;
    cudaGetSymbolAddress(&p, g_qh);  bf16* qh  = (bf16*)p;
    cudaGetSymbolAddress(&p, g_ql);  bf16* ql  = (bf16*)p;
    cudaGetSymbolAddress(&p, g_att); float* attp = (float*)p;
    cudaGetSymbolAddress(&p, g_ah);  bf16* ath = (bf16*)p;
    cudaGetSymbolAddress(&p, g_al);  bf16* atl = (bf16*)p;
    cudaGetSymbolAddress(&p, g_yh);  bf16* yh  = (bf16*)p;
    cudaGetSymbolAddress(&p, g_yl);  bf16* yl  = (bf16*)p;
    cudaGetSymbolAddress(&p, g_wph); bf16* wph = (bf16*)p;
    cudaGetSymbolAddress(&p, g_wpl); bf16* wpl = (bf16*)p;

    const size_t QKV_N = (size_t)NB * CCH * HW;
    const size_t ATT_N = (size_t)NB * NHD * 512 * 512;

    cudaFuncSetAttribute(conv_mma_kernel, cudaFuncAttributeMaxDynamicSharedMemorySize, SM4);
    cudaFuncSetAttribute(qk_mma_kernel,   cudaFuncAttributeMaxDynamicSharedMemorySize, SM4);
    cudaFuncSetAttribute(av_mma_kernel,   cudaFuncAttributeMaxDynamicSharedMemorySize, SMT);
    cudaFuncSetAttribute(proj_mma_kernel, cudaFuncAttributeMaxDynamicSharedMemorySize, SMT);

    prep_w3<<<dim3(1024, 6), 256>>>(
        (const float*)d_in[2], (const float*)d_in[3], (const float*)d_in[4],
        (const float*)d_in[5], (const float*)d_in[6], (const float*)d_in[7], wh, wl);
    prep_wp<<<dim3(1024, 2), 256>>>(Wp1, Wp2, wph, wpl);
    transpose_x<<<dim3(32, 16, 8), dim3(32, 8)>>>(x_l, x_g, xh, xl);

    conv_mma_kernel<<<dim3(8, 4, 24), 256, SM4>>>(xh, xl, wh, wl, qh, ql);

    // buffers: 0 kl, 1 ql, 2 vl, 3 kg, 4 qg, 5 vg
    dim3 gqk(4, 4, 32);
    qk_mma_kernel<<<gqk, 256, SM4>>>(qh + 4 * QKV_N, ql + 4 * QKV_N,
                                     qh + 0 * QKV_N, ql + 0 * QKV_N, attp);          // q_g,k_l
    qk_mma_kernel<<<gqk, 256, SM4>>>(qh + 1 * QKV_N, ql + 1 * QKV_N,
                                     qh + 3 * QKV_N, ql + 3 * QKV_N, attp + ATT_N);  // q_l,k_g

    softmax_kernel<<<2048, 256>>>(attp,         ath,         atl);
    softmax_kernel<<<2048, 256>>>(attp + ATT_N, ath + ATT_N, atl + ATT_N);

    dim3 gav(4, 32);
    av_mma_kernel<<<gav, 256, SMT>>>(ath, atl, qh + 2 * QKV_N, ql + 2 * QKV_N,
                                     yh, yl);                       // y_g = att_g @ v_l
    av_mma_kernel<<<gav, 256, SMT>>>(ath + ATT_N, atl + ATT_N,
                                     qh + 5 * QKV_N, ql + 5 * QKV_N,
                                     yh + QKV_N, yl + QKV_N);       // y_l = att_l @ v_g

    dim3 gproj(8, 4, 4);
    proj_mma_kernel<<<gproj, 256, SMT>>>(yh + QKV_N, yl + QKV_N, wph, wpl,
                                         x_l, rw, out_l);           // Wp1 on y_l
    proj_mma_kernel<<<gproj, 256, SMT>>>(yh, yl, wph + 512 * 512, wpl + 512 * 512,
                                         x_g, rw, out_g);           // Wp2 on y_g
}

// round 8
// speedup vs baseline: 1.6811x; 1.6811x over previous
#include <cuda_runtime.h>
#include <cuda_bf16.h>
#include <cstdint>

// ---------------------------------------------------------------------------
// CrossAttention on GB300 (sm_103a; plain compute_103 target -> mma.sync bf16).
// All GEMMs: m16n8k16 bf16 3-term hi/lo split (AhBh+AhBl+AlBh, fp32 accum).
// R8: conv = R7-style cp.async double-buffered pipeline (cg->ca, bf16 hi/lo
// operands pre-converted, fp32 output). qk/av/proj/softmax = exact R6 kernels.
// ---------------------------------------------------------------------------

#define NB   4
#define CCH  512
#define HW   1024
#define NHD  8
#define DHEAD 128

typedef __nv_bfloat16 bf16;

// Scratch (no allocations -> __device__ globals)
__device__ bf16  g_wh[6][9 * 512 * 512], g_wl[6][9 * 512 * 512];   // [r][co][ci]
__device__ bf16  g_xh[2][NB * HW * CCH], g_xl[2][NB * HW * CCH];   // [n][hw][ci]
__device__ float g_qkv[6][NB * CCH * HW];                          // kl,ql,vl,kg,qg,vg
__device__ float g_att[2][NB * NHD * 512 * 512];                   // att_g, att_l
__device__ float g_y[2][NB * CCH * HW];                            // y_g, y_l

// ============================ helpers =======================================
__device__ __forceinline__ uint32_t smem_u32(const void* p) {
    uint32_t a;
    asm("{ .reg .u64 t; cvta.to.shared.u64 t, %1; cvt.u32.u64 %0, t; }"
        : "=r"(a) : "l"(p));
    return a;
}

__device__ __forceinline__ void mma_bf16(float* c, const uint32_t* a, const uint32_t* b) {
    asm volatile(
        "mma.sync.aligned.m16n8k16.row.col.f32.bf16.bf16.f32 "
        "{%0,%1,%2,%3}, {%4,%5,%6,%7}, {%8,%9}, {%0,%1,%2,%3};"
        : "+f"(c[0]), "+f"(c[1]), "+f"(c[2]), "+f"(c[3])
        : "r"(a[0]), "r"(a[1]), "r"(a[2]), "r"(a[3]), "r"(b[0]), "r"(b[1]));
}

#define LDSM4(r0, r1, r2, r3, addr) \
    asm volatile("ldmatrix.sync.aligned.m8n8.x4.shared.b16 {%0,%1,%2,%3}, [%4];" \
                 : "=r"(r0), "=r"(r1), "=r"(r2), "=r"(r3) : "r"(addr))

#define LDSM2T(r0, r1, addr) \
    asm volatile("ldmatrix.sync.aligned.m8n8.x2.trans.shared.b16 {%0,%1}, [%2];" \
                 : "=r"(r0), "=r"(r1) : "r"(addr))

#define STS64(addr, v0, v1) \
    asm volatile("st.shared.v2.u32 [%0], {%1,%2};" :: "r"(addr), "r"(v0), "r"(v1) : "memory")

// cp.async with L1 enabled (ca) — keeps cross-CTA weight reuse in L1
#define CPA(dst, src, sz) \
    asm volatile("cp.async.ca.shared.global [%0], [%1], 16, %2;" \
                 :: "r"(dst), "l"(src), "r"(sz) : "memory")
#define CP_COMMIT() asm volatile("cp.async.commit_group;" ::: "memory")
#define CP_WAIT1()  asm volatile("cp.async.wait_group 1;" ::: "memory")
#define CP_WAIT0()  asm volatile("cp.async.wait_group 0;" ::: "memory")

// fp32x4 -> bf16 hi/lo packed pairs (for R6-style in-loop conversion)
__device__ __forceinline__ void hilo4(float4 v, uint32_t h[2], uint32_t l[2]) {
    __nv_bfloat162 h01 = __floats2bfloat162_rn(v.x, v.y);
    __nv_bfloat162 h23 = __floats2bfloat162_rn(v.z, v.w);
    float2 f01 = __bfloat1622float2(h01);
    float2 f23 = __bfloat1622float2(h23);
    __nv_bfloat162 l01 = __floats2bfloat162_rn(v.x - f01.x, v.y - f01.y);
    __nv_bfloat162 l23 = __floats2bfloat162_rn(v.z - f23.x, v.w - f23.y);
    h[0] = *(uint32_t*)&h01; h[1] = *(uint32_t*)&h23;
    l[0] = *(uint32_t*)&l01; l[1] = *(uint32_t*)&l23;
}
__device__ __forceinline__ void scalar_hilo(float v, bf16& h, bf16& l) {
    h = __float2bfloat16_rn(v);
    l = __float2bfloat16_rn(v - __bfloat162float(h));
}

// ============================ prep kernels ==================================
// w [co][ci][3][3] -> [conv][r][co][ci] bf16 hi/lo
__global__ void prep_w3(const float* __restrict__ w0, const float* __restrict__ w1,
                        const float* __restrict__ w2, const float* __restrict__ w3,
                        const float* __restrict__ w4, const float* __restrict__ w5,
                        bf16* __restrict__ wh, bf16* __restrict__ wl) {
    const float* ws[6] = {w0, w1, w2, w3, w4, w5};
    int conv = blockIdx.y;
    const float* w = ws[conv];
    int t = blockIdx.x * 256 + threadIdx.x;
    int co = t >> 9, ci = t & 511;
    float v[9];
#pragma unroll
    for (int r = 0; r < 9; ++r) v[r] = w[(size_t)t * 9 + r];
#pragma unroll
    for (int r = 0; r < 9; ++r) {
        size_t o = (((size_t)conv * 9 + r) * 512 + co) * 512 + ci;
        bf16 h, l; scalar_hilo(v[r], h, l);
        wh[o] = h; wl[o] = l;
    }
}
// x [n][c][hw] -> xt [n][hw][c] bf16 hi/lo
__global__ void transpose_x(const float* __restrict__ xl, const float* __restrict__ xg,
                            bf16* __restrict__ xth, bf16* __restrict__ xtl) {
    __shared__ float tile[32][33];
    int zt = blockIdx.z, tsel = zt >> 2, n = zt & 3;
    const float* x = (tsel ? xg : xl) + (size_t)n * (CCH * HW);
    size_t ob = (size_t)tsel * NB * HW * CCH + (size_t)n * (HW * CCH);
    int hw0 = blockIdx.x * 32, c0 = blockIdx.y * 32;
    int tx = threadIdx.x, ty = threadIdx.y;
#pragma unroll
    for (int i = 0; i < 32; i += 8)
        tile[ty + i][tx] = x[(size_t)(c0 + ty + i) * HW + hw0 + tx];
    __syncthreads();
#pragma unroll
    for (int i = 0; i < 32; i += 8) {
        float v = tile[tx][ty + i];
        bf16 h, l; scalar_hilo(v, h, l);
        size_t o = ob + (size_t)(hw0 + ty + i) * CCH + c0 + tx;
        xth[o] = h; xtl[o] = l;
    }
}

// ============================ layout consts =================================
#define ROWB 80                     // 32 bf16 (64B) + 16B pad
#define MATB (128 * ROWB)           // 10240
#define ROW2 272                    // 128 bf16 (256B) + 16B pad
#define MATB2 (32 * ROW2)           // 8704
#define STG4 (4 * MATB)             // conv stage: Ah Al Bh Bl  40960
#define SM4  (2 * STG4)             // 81920 (2-stage double buffer)

// ================== conv 3x3: cp.async.ca 2-stage + mma =====================
// grid (8 s-tiles, 4 co-tiles, 24 conv*n), 256 threads, 2 CTAs/SM.
// Output fp32 (consumed by R6-style attention kernels).
__global__ __launch_bounds__(256, 2)
void conv_mma_kernel(const bf16* __restrict__ xth, const bf16* __restrict__ xtl,
                     const bf16* __restrict__ wh, const bf16* __restrict__ wl,
                     float* __restrict__ qkv) {
    extern __shared__ unsigned char dsm[];
    const uint32_t sb = smem_u32(dsm);

    int tid = threadIdx.x, wid = tid >> 5, lid = tid & 31;
    int warp_m = wid >> 2, warp_n = wid & 3;
    int sp0 = blockIdx.x * 128, co0 = blockIdx.y * 128;
    int conv = blockIdx.z >> 2, n = blockIdx.z & 3;
    size_t xoffb = ((size_t)(conv < 3 ? 0 : 1) * NB + n) * (HW * CCH);
    const bf16* xh = xth + xoffb;
    const bf16* xl = xtl + xoffb;
    const bf16* wbh = wh + (size_t)conv * (9 * 512 * 512);
    const bf16* wbl = wl + (size_t)conv * (9 * 512 * 512);
    float* outb = qkv + ((size_t)conv * NB + n) * (CCH * HW);

    float acc[4][4][4];
#pragma unroll
    for (int mt = 0; mt < 4; ++mt)
#pragma unroll
        for (int nt = 0; nt < 4; ++nt)
#pragma unroll
            for (int k = 0; k < 4; ++k) acc[mt][nt][k] = 0.f;

    int grp = lid >> 3, lr = lid & 7;
    uint32_t a_base = (uint32_t)((warp_m * 64 + (grp & 1) * 8 + lr) * ROWB + (grp >> 1) * 16);
    uint32_t b_base = (uint32_t)((warp_n * 32 + (grp & 1) * 8 + lr) * ROWB + (grp >> 1) * 16);

    int row = tid >> 1, half = tid & 1;
    uint32_t dstA = (uint32_t)(row * ROWB + half * 32);

    auto prefetch = [&](int ch, int st) {
        uint32_t s0b = sb + st * STG4;
        int r = ch >> 4, ci0 = (ch & 15) << 5;
        int dy = r / 3 - 1, dx = r % 3 - 1;
        size_t wof = ((size_t)r * 512 + co0 + row) * 512 + ci0 + half * 16;
        uint32_t da = s0b + dstA;
        CPA(da,             wbh + wof,     16u);
        CPA(da + 16,        wbh + wof + 8, 16u);
        CPA(da + MATB,      wbl + wof,     16u);
        CPA(da + MATB + 16, wbl + wof + 8, 16u);
        int s = sp0 + row;
        int yy = (s >> 5) + dy, xx = (s & 31) + dx;
        bool ok = ((unsigned)yy < 32u) && ((unsigned)xx < 32u);
        size_t xof = ok ? ((size_t)(yy * 32 + xx) * 512 + ci0 + half * 16) : 0;
        uint32_t sz = ok ? 16u : 0u;
        uint32_t db = s0b + 2 * MATB + dstA;
        CPA(db,             xh + xof,     sz);
        CPA(db + 16,        xh + xof + 8, sz);
        CPA(db + MATB,      xl + xof,     sz);
        CPA(db + MATB + 16, xl + xof + 8, sz);
    };

    prefetch(0, 0); CP_COMMIT();
    for (int ch = 0; ch < 144; ++ch) {
        if (ch + 1 < 144) { prefetch(ch + 1, (ch + 1) & 1); CP_COMMIT(); CP_WAIT1(); }
        else CP_WAIT0();
        __syncthreads();
        uint32_t st = sb + (ch & 1) * STG4;
        uint32_t sAh = st, sAl = st + MATB, sBh = st + 2 * MATB, sBl = st + 3 * MATB;
#pragma unroll
        for (int kt = 0; kt < 2; ++kt) {
            uint32_t aH[4][4], aL[4][4], bH[4][2], bL[4][2];
#pragma unroll
            for (int mt = 0; mt < 4; ++mt) {
                uint32_t ad = a_base + (uint32_t)(mt * 16 * ROWB + kt * 32);
                LDSM4(aH[mt][0], aH[mt][1], aH[mt][2], aH[mt][3], sAh + ad);
                LDSM4(aL[mt][0], aL[mt][1], aL[mt][2], aL[mt][3], sAl + ad);
            }
#pragma unroll
            for (int p = 0; p < 2; ++p) {
                uint32_t bd = b_base + (uint32_t)(p * 16 * ROWB + kt * 32);
                uint32_t r0, r1, r2, r3;
                LDSM4(r0, r1, r2, r3, sBh + bd);
                bH[2 * p][0] = r0; bH[2 * p][1] = r2;
                bH[2 * p + 1][0] = r1; bH[2 * p + 1][1] = r3;
                LDSM4(r0, r1, r2, r3, sBl + bd);
                bL[2 * p][0] = r0; bL[2 * p][1] = r2;
                bL[2 * p + 1][0] = r1; bL[2 * p + 1][1] = r3;
            }
#pragma unroll
            for (int mt = 0; mt < 4; ++mt)
#pragma unroll
                for (int nt = 0; nt < 4; ++nt) {
                    mma_bf16(acc[mt][nt], aH[mt], bH[nt]);
                    mma_bf16(acc[mt][nt], aH[mt], bL[nt]);
                    mma_bf16(acc[mt][nt], aL[mt], bH[nt]);
                }
        }
        __syncthreads();
    }

#pragma unroll
    for (int mt = 0; mt < 4; ++mt) {
        int m = co0 + warp_m * 64 + mt * 16 + (lid >> 2);
#pragma unroll
        for (int nt = 0; nt < 4; ++nt) {
            int sc = sp0 + warp_n * 32 + nt * 8 + (lid & 3) * 2;
            *(float2*)(outb + (size_t)m * HW + sc) =
                make_float2(acc[mt][nt][0], acc[mt][nt][1]);
            *(float2*)(outb + (size_t)(m + 8) * HW + sc) =
                make_float2(acc[mt][nt][2], acc[mt][nt][3]);
        }
    }
}

// ======================== QK^T (exact R6 kernel) ============================
__global__ __launch_bounds__(256)
void qk_mma_kernel(const float* __restrict__ q, const float* __restrict__ k,
                   float* __restrict__ att) {
    __shared__ __align__(16) unsigned char sm[4 * MATB];
    const uint32_t sb  = smem_u32(sm);
    const uint32_t sAh = sb, sAl = sb + MATB, sBh = sb + 2 * MATB, sBl = sb + 3 * MATB;

    int tid = threadIdx.x, wid = tid >> 5, lid = tid & 31;
    int warp_m = wid >> 2, warp_n = wid & 3;
    int nh = blockIdx.z, n = nh >> 3, h = nh & 7;
    int ck0 = blockIdx.x * 128, cq0 = blockIdx.y * 128;
    const float* qb = q + (size_t)n * (CCH * HW) + h * DHEAD;
    const float* kb = k + (size_t)n * (CCH * HW) + h * DHEAD;

    float acc[4][4][4];
#pragma unroll
    for (int mt = 0; mt < 4; ++mt)
#pragma unroll
        for (int nt = 0; nt < 4; ++nt)
#pragma unroll
            for (int kk = 0; kk < 4; ++kk) acc[mt][nt][kk] = 0.f;

    int grp = lid >> 3, lr = lid & 7;
    uint32_t a_base = (uint32_t)((warp_m * 64 + (grp & 1) * 8 + lr) * ROWB + (grp >> 1) * 16);
    uint32_t b_base = (uint32_t)((warp_n * 32 + (grp & 1) * 8 + lr) * ROWB + (grp >> 1) * 16);

    int row = tid >> 1, kh = tid & 1;
    uint32_t so = (uint32_t)(row * ROWB + kh * 32);
    float4 ra[4], rb[4];

    auto stage = [&](int ch) {
        int ci0 = ch << 5;
        const float* qr = qb + (size_t)(cq0 + row) * HW + ci0 + kh * 16;
        const float* kr = kb + (size_t)(ck0 + row) * HW + ci0 + kh * 16;
#pragma unroll
        for (int j = 0; j < 4; ++j) ra[j] = *(const float4*)(qr + 4 * j);
#pragma unroll
        for (int j = 0; j < 4; ++j) rb[j] = *(const float4*)(kr + 4 * j);
    };

    stage(0);
    for (int ch = 0; ch < 4; ++ch) {
#pragma unroll
        for (int j = 0; j < 4; ++j) {
            uint32_t h2[2], l2[2];
            hilo4(ra[j], h2, l2);
            STS64(sAh + so + j * 8, h2[0], h2[1]);
            STS64(sAl + so + j * 8, l2[0], l2[1]);
        }
#pragma unroll
        for (int j = 0; j < 4; ++j) {
            uint32_t h2[2], l2[2];
            hilo4(rb[j], h2, l2);
            STS64(sBh + so + j * 8, h2[0], h2[1]);
            STS64(sBl + so + j * 8, l2[0], l2[1]);
        }
        __syncthreads();
        if (ch + 1 < 4) stage(ch + 1);

#pragma unroll
        for (int kt = 0; kt < 2; ++kt) {
            uint32_t aH[4][4], aL[4][4], bH[4][2], bL[4][2];
#pragma unroll
            for (int mt = 0; mt < 4; ++mt) {
                uint32_t ad = a_base + (uint32_t)(mt * 16 * ROWB + kt * 32);
                LDSM4(aH[mt][0], aH[mt][1], aH[mt][2], aH[mt][3], sAh + ad);
                LDSM4(aL[mt][0], aL[mt][1], aL[mt][2], aL[mt][3], sAl + ad);
            }
#pragma unroll
            for (int p = 0; p < 2; ++p) {
                uint32_t bd = b_base + (uint32_t)(p * 16 * ROWB + kt * 32);
                uint32_t r0, r1, r2, r3;
                LDSM4(r0, r1, r2, r3, sBh + bd);
                bH[2 * p][0] = r0; bH[2 * p][1] = r2;
                bH[2 * p + 1][0] = r1; bH[2 * p + 1][1] = r3;
                LDSM4(r0, r1, r2, r3, sBl + bd);
                bL[2 * p][0] = r0; bL[2 * p][1] = r2;
                bL[2 * p + 1][0] = r1; bL[2 * p + 1][1] = r3;
            }
#pragma unroll
            for (int mt = 0; mt < 4; ++mt)
#pragma unroll
                for (int nt = 0; nt < 4; ++nt) {
                    mma_bf16(acc[mt][nt], aH[mt], bH[nt]);
                    mma_bf16(acc[mt][nt], aH[mt], bL[nt]);
                    mma_bf16(acc[mt][nt], aL[mt], bH[nt]);
                }
        }
        __syncthreads();
    }

    const float SC = 0.08838834764831845f;   // 1/sqrt(128)
    float* ab = att + (size_t)(n * NHD + h) * 512 * 512;
#pragma unroll
    for (int mt = 0; mt < 4; ++mt) {
        int m = cq0 + warp_m * 64 + mt * 16 + (lid >> 2);
#pragma unroll
        for (int nt = 0; nt < 4; ++nt) {
            int sc = ck0 + warp_n * 32 + nt * 8 + (lid & 3) * 2;
            *(float2*)(ab + (size_t)m * 512 + sc) =
                make_float2(acc[mt][nt][0] * SC, acc[mt][nt][1] * SC);
            *(float2*)(ab + (size_t)(m + 8) * 512 + sc) =
                make_float2(acc[mt][nt][2] * SC, acc[mt][nt][3] * SC);
        }
    }
}

// ------------------------------- softmax (R6) --------------------------------
__global__ void softmax_kernel(float* __restrict__ att) {
    int row  = blockIdx.x * 8 + (threadIdx.x >> 5);
    int lane = threadIdx.x & 31;
    float* p = att + (size_t)row * 512;
    float v[16];
    float m = -1e30f;
#pragma unroll
    for (int i = 0; i < 16; ++i) { v[i] = p[lane + i * 32]; m = fmaxf(m, v[i]); }
#pragma unroll
    for (int o = 16; o; o >>= 1) m = fmaxf(m, __shfl_xor_sync(0xffffffffu, m, o));
    float s = 0.f;
#pragma unroll
    for (int i = 0; i < 16; ++i) { v[i] = __expf(v[i] - m); s += v[i]; }
#pragma unroll
    for (int o = 16; o; o >>= 1) s += __shfl_xor_sync(0xffffffffu, s, o);
    float inv = 1.f / s;
#pragma unroll
    for (int i = 0; i < 16; ++i) p[lane + i * 32] = v[i] * inv;
}

// ===================== AV (exact R6 kernel, B trans) ========================
__global__ __launch_bounds__(256)
void av_mma_kernel(const float* __restrict__ att, const float* __restrict__ v,
                   float* __restrict__ y) {
    __shared__ __align__(16) unsigned char sm[2 * MATB + 2 * MATB2];
    const uint32_t sb  = smem_u32(sm);
    const uint32_t sAh = sb, sAl = sb + MATB;
    const uint32_t sBh = sb + 2 * MATB, sBl = sb + 2 * MATB + MATB2;

    int tid = threadIdx.x, wid = tid >> 5, lid = tid & 31;
    int warp_m = wid >> 2, warp_n = wid & 3;
    int nh = blockIdx.y, n = nh >> 3, h = nh & 7;
    int cq0 = blockIdx.x * 128;
    const float* ab = att + (size_t)(n * NHD + h) * 512 * 512;
    const float* vb = v + (size_t)n * (CCH * HW) + h * DHEAD;

    float acc[4][4][4];
#pragma unroll
    for (int mt = 0; mt < 4; ++mt)
#pragma unroll
        for (int nt = 0; nt < 4; ++nt)
#pragma unroll
            for (int kk = 0; kk < 4; ++kk) acc[mt][nt][kk] = 0.f;

    int grp = lid >> 3, lr = lid & 7;
    uint32_t a_base = (uint32_t)((warp_m * 64 + (grp & 1) * 8 + lr) * ROWB + (grp >> 1) * 16);
    int l16 = lid & 15;
    uint32_t bt_base = (uint32_t)(l16 * ROW2 + warp_n * 64);

    int row = tid >> 1, kh = tid & 1;
    uint32_t soA = (uint32_t)(row * ROWB + kh * 32);
    int ckr = tid >> 3, dseg = (tid & 7) * 16;
    uint32_t soB = (uint32_t)(ckr * ROW2 + dseg * 2);
    float4 ra[4], rb[4];

    auto stage = [&](int ch) {
        int ci0 = ch << 5;
        const float* ar = ab + (size_t)(cq0 + row) * 512 + ci0 + kh * 16;
#pragma unroll
        for (int j = 0; j < 4; ++j) ra[j] = *(const float4*)(ar + 4 * j);
        const float* vr = vb + (size_t)(ci0 + ckr) * HW + dseg;
#pragma unroll
        for (int j = 0; j < 4; ++j) rb[j] = *(const float4*)(vr + 4 * j);
    };

    stage(0);
    for (int ch = 0; ch < 16; ++ch) {
#pragma unroll
        for (int j = 0; j < 4; ++j) {
            uint32_t h2[2], l2[2];
            hilo4(ra[j], h2, l2);
            STS64(sAh + soA + j * 8, h2[0], h2[1]);
            STS64(sAl + soA + j * 8, l2[0], l2[1]);
        }
#pragma unroll
        for (int j = 0; j < 4; ++j) {
            uint32_t h2[2], l2[2];
            hilo4(rb[j], h2, l2);
            STS64(sBh + soB + j * 8, h2[0], h2[1]);
            STS64(sBl + soB + j * 8, l2[0], l2[1]);
        }
        __syncthreads();
        if (ch + 1 < 16) stage(ch + 1);

#pragma unroll
        for (int kt = 0; kt < 2; ++kt) {
            uint32_t aH[4][4], aL[4][4], bH[4][2], bL[4][2];
#pragma unroll
            for (int mt = 0; mt < 4; ++mt) {
                uint32_t ad = a_base + (uint32_t)(mt * 16 * ROWB + kt * 32);
                LDSM4(aH[mt][0], aH[mt][1], aH[mt][2], aH[mt][3], sAh + ad);
                LDSM4(aL[mt][0], aL[mt][1], aL[mt][2], aL[mt][3], sAl + ad);
            }
#pragma unroll
            for (int nt = 0; nt < 4; ++nt) {
                uint32_t bd = bt_base + (uint32_t)(kt * 16 * ROW2 + nt * 16);
                LDSM2T(bH[nt][0], bH[nt][1], sBh + bd);
                LDSM2T(bL[nt][0], bL[nt][1], sBl + bd);
            }
#pragma unroll
            for (int mt = 0; mt < 4; ++mt)
#pragma unroll
                for (int nt = 0; nt < 4; ++nt) {
                    mma_bf16(acc[mt][nt], aH[mt], bH[nt]);
                    mma_bf16(acc[mt][nt], aH[mt], bL[nt]);
                    mma_bf16(acc[mt][nt], aL[mt], bH[nt]);
                }
        }
        __syncthreads();
    }

    float* yb = y + (size_t)n * (CCH * HW) + h * DHEAD;
#pragma unroll
    for (int mt = 0; mt < 4; ++mt) {
        int m = cq0 + warp_m * 64 + mt * 16 + (lid >> 2);
#pragma unroll
        for (int nt = 0; nt < 4; ++nt) {
            int dc = warp_n * 32 + nt * 8 + (lid & 3) * 2;
            *(float2*)(yb + (size_t)m * HW + dc) =
                make_float2(acc[mt][nt][0], acc[mt][nt][1]);
            *(float2*)(yb + (size_t)(m + 8) * HW + dc) =
                make_float2(acc[mt][nt][2], acc[mt][nt][3]);
        }
    }
}

// ============ 1x1 proj + residual (exact R6 kernel, B trans) ================
__global__ __launch_bounds__(256)
void proj_mma_kernel(const float* __restrict__ y, const float* __restrict__ wp,
                     const float* __restrict__ xres, const float* __restrict__ rwp,
                     float* __restrict__ out) {
    __shared__ __align__(16) unsigned char sm[2 * MATB + 2 * MATB2];
    const uint32_t sb  = smem_u32(sm);
    const uint32_t sAh = sb, sAl = sb + MATB;
    const uint32_t sBh = sb + 2 * MATB, sBl = sb + 2 * MATB + MATB2;

    int tid = threadIdx.x, wid = tid >> 5, lid = tid & 31;
    int warp_m = wid >> 2, warp_n = wid & 3;
    int s0 = blockIdx.x * 128, co0 = blockIdx.y * 128, n = blockIdx.z;
    const float* yb = y + (size_t)n * (CCH * HW);

    float acc[4][4][4];
#pragma unroll
    for (int mt = 0; mt < 4; ++mt)
#pragma unroll
        for (int nt = 0; nt < 4; ++nt)
#pragma unroll
            for (int kk = 0; kk < 4; ++kk) acc[mt][nt][kk] = 0.f;

    int grp = lid >> 3, lr = lid & 7;
    uint32_t a_base = (uint32_t)((warp_m * 64 + (grp & 1) * 8 + lr) * ROWB + (grp >> 1) * 16);
    int l16 = lid & 15;
    uint32_t bt_base = (uint32_t)(l16 * ROW2 + warp_n * 64);

    int row = tid >> 1, kh = tid & 1;
    uint32_t soA = (uint32_t)(row * ROWB + kh * 32);
    int cir = tid >> 3, sseg = (tid & 7) * 16;
    uint32_t soB = (uint32_t)(cir * ROW2 + sseg * 2);
    float4 ra[4], rb[4];

    auto stage = [&](int ch) {
        int ci0 = ch << 5;
        const float* wr = wp + (size_t)(co0 + row) * 512 + ci0 + kh * 16;
#pragma unroll
        for (int j = 0; j < 4; ++j) ra[j] = *(const float4*)(wr + 4 * j);
        const float* yr = yb + (size_t)(ci0 + cir) * HW + s0 + sseg;
#pragma unroll
        for (int j = 0; j < 4; ++j) rb[j] = *(const float4*)(yr + 4 * j);
    };

    stage(0);
    for (int ch = 0; ch < 16; ++ch) {
#pragma unroll
        for (int j = 0; j < 4; ++j) {
            uint32_t h2[2], l2[2];
            hilo4(ra[j], h2, l2);
            STS64(sAh + soA + j * 8, h2[0], h2[1]);
            STS64(sAl + soA + j * 8, l2[0], l2[1]);
        }
#pragma unroll
        for (int j = 0; j < 4; ++j) {
            uint32_t h2[2], l2[2];
            hilo4(rb[j], h2, l2);
            STS64(sBh + soB + j * 8, h2[0], h2[1]);
            STS64(sBl + soB + j * 8, l2[0], l2[1]);
        }
        __syncthreads();
        if (ch + 1 < 16) stage(ch + 1);

#pragma unroll
        for (int kt = 0; kt < 2; ++kt) {
            uint32_t aH[4][4], aL[4][4], bH[4][2], bL[4][2];
#pragma unroll
            for (int mt = 0; mt < 4; ++mt) {
                uint32_t ad = a_base + (uint32_t)(mt * 16 * ROWB + kt * 32);
                LDSM4(aH[mt][0], aH[mt][1], aH[mt][2], aH[mt][3], sAh + ad);
                LDSM4(aL[mt][0], aL[mt][1], aL[mt][2], aL[mt][3], sAl + ad);
            }
#pragma unroll
            for (int nt = 0; nt < 4; ++nt) {
                uint32_t bd = bt_base + (uint32_t)(kt * 16 * ROW2 + nt * 16);
                LDSM2T(bH[nt][0], bH[nt][1], sBh + bd);
                LDSM2T(bL[nt][0], bL[nt][1], sBl + bd);
            }
#pragma unroll
            for (int mt = 0; mt < 4; ++mt)
#pragma unroll
                for (int nt = 0; nt < 4; ++nt) {
                    mma_bf16(acc[mt][nt], aH[mt], bH[nt]);
                    mma_bf16(acc[mt][nt], aH[mt], bL[nt]);
                    mma_bf16(acc[mt][nt], aL[mt], bH[nt]);
                }
        }
        __syncthreads();
    }

    float rw = *rwp;
#pragma unroll
    for (int mt = 0; mt < 4; ++mt) {
        int m = co0 + warp_m * 64 + mt * 16 + (lid >> 2);
#pragma unroll
        for (int nt = 0; nt < 4; ++nt) {
            int sc = s0 + warp_n * 32 + nt * 8 + (lid & 3) * 2;
            size_t b0 = ((size_t)n * CCH + m) * HW + sc;
            size_t b1 = ((size_t)n * CCH + m + 8) * HW + sc;
            float2 x0 = *(const float2*)(xres + b0);
            float2 x1 = *(const float2*)(xres + b1);
            *(float2*)(out + b0) = make_float2(x0.x + rw * acc[mt][nt][0],
                                               x0.y + rw * acc[mt][nt][1]);
            *(float2*)(out + b1) = make_float2(x1.x + rw * acc[mt][nt][2],
                                               x1.y + rw * acc[mt][nt][3]);
        }
    }
}

// ------------------------------- launcher -----------------------------------
extern "C" void kernel_launch(void* const* d_in, const int* in_sizes, int n_in,
                              void* d_out, int out_size) {
    (void)in_sizes; (void)n_in; (void)out_size;
    const float* x_l = (const float*)d_in[0];
    const float* x_g = (const float*)d_in[1];
    const float* Wp1 = (const float*)d_in[8];
    const float* Wp2 = (const float*)d_in[9];
    const float* rw  = (const float*)d_in[10];
    float* out_l = (float*)d_out;
    float* out_g = out_l + (size_t)NB * CCH * HW;

    void* p;
    cudaGetSymbolAddress(&p, g_wh);  bf16* wh  = (bf16*)p;
    cudaGetSymbolAddress(&p, g_wl);  bf16* wl  = (bf16*)p;
    cudaGetSymbolAddress(&p, g_xh);  bf16* xh  = (bf16*)p;
    cudaGetSymbolAddress(&p, g_xl);  bf16* xl  = (bf16*)p;
    cudaGetSymbolAddress(&p, g_qkv); float* qkv = (float*)p;
    cudaGetSymbolAddress(&p, g_att); float* attp = (float*)p;
    cudaGetSymbolAddress(&p, g_y);   float* yb  = (float*)p;

    const size_t QKV_N = (size_t)NB * CCH * HW;
    const size_t ATT_N = (size_t)NB * NHD * 512 * 512;

    cudaFuncSetAttribute(conv_mma_kernel, cudaFuncAttributeMaxDynamicSharedMemorySize, SM4);

    prep_w3<<<dim3(1024, 6), 256>>>(
        (const float*)d_in[2], (const float*)d_in[3], (const float*)d_in[4],
        (const float*)d_in[5], (const float*)d_in[6], (const float*)d_in[7], wh, wl);
    transpose_x<<<dim3(32, 16, 8), dim3(32, 8)>>>(x_l, x_g, xh, xl);

    // buffers: 0 kl, 1 ql, 2 vl, 3 kg, 4 qg, 5 vg
    conv_mma_kernel<<<dim3(8, 4, 24), 256, SM4>>>(xh, xl, wh, wl, qkv);

    dim3 gqk(4, 4, 32);
    qk_mma_kernel<<<gqk, 256>>>(qkv + 4 * QKV_N, qkv + 0 * QKV_N, attp);          // q_g,k_l
    qk_mma_kernel<<<gqk, 256>>>(qkv + 1 * QKV_N, qkv + 3 * QKV_N, attp + ATT_N);  // q_l,k_g

    softmax_kernel<<<2048, 256>>>(attp);
    softmax_kernel<<<2048, 256>>>(attp + ATT_N);

    dim3 gav(4, 32);
    av_mma_kernel<<<gav, 256>>>(attp,         qkv + 2 * QKV_N, yb);           // y_g
    av_mma_kernel<<<gav, 256>>>(attp + ATT_N, qkv + 5 * QKV_N, yb + QKV_N);   // y_l

    dim3 gproj(8, 4, 4);
    proj_mma_kernel<<<gproj, 256>>>(yb + QKV_N, Wp1, x_l, rw, out_l);
    proj_mma_kernel<<<gproj, 256>>>(yb,         Wp2, x_g, rw, out_g);
}

// round 9
// speedup vs baseline: 1.7511x; 1.0416x over previous
#include <cuda_runtime.h>
#include <cuda_bf16.h>
#include <cstdint>

// ---------------------------------------------------------------------------
// CrossAttention on GB300 (sm_103a; plain compute_103 -> mma.sync bf16).
// All GEMMs: m16n8k16 bf16 3-term hi/lo split (AhBh+AhBl+AlBh, fp32 accum).
// R9: conv/qk/av/proj all cp.async.ca double-buffered; operands pre-converted
// to bf16 hi/lo at producers; merged launches. qk uses (256,2) (conv-proven);
// av/proj use plain 256 (no reg cap -> no spills, the R7 failure mode).
// ---------------------------------------------------------------------------

#define NB   4
#define CCH  512
#define HW   1024
#define NHD  8
#define DHEAD 128

typedef __nv_bfloat16 bf16;

// Scratch (no allocations -> __device__ globals)
__device__ bf16  g_wh[6][9 * 512 * 512], g_wl[6][9 * 512 * 512];   // [r][co][ci]
__device__ bf16  g_xh[2][NB * HW * CCH], g_xl[2][NB * HW * CCH];   // [n][hw][ci]
__device__ bf16  g_qh[6][NB * CCH * HW], g_ql[6][NB * CCH * HW];   // qkv hi/lo
__device__ float g_att[2][NB * NHD * 512 * 512];                   // pre-softmax
__device__ bf16  g_ah[2][NB * NHD * 512 * 512], g_al[2][NB * NHD * 512 * 512];
__device__ bf16  g_yh[2][NB * CCH * HW], g_yl[2][NB * CCH * HW];   // y_g, y_l
__device__ bf16  g_wph[2][512 * 512], g_wpl[2][512 * 512];

// ============================ helpers =======================================
__device__ __forceinline__ uint32_t smem_u32(const void* p) {
    uint32_t a;
    asm("{ .reg .u64 t; cvta.to.shared.u64 t, %1; cvt.u32.u64 %0, t; }"
        : "=r"(a) : "l"(p));
    return a;
}

__device__ __forceinline__ void mma_bf16(float* c, const uint32_t* a, const uint32_t* b) {
    asm volatile(
        "mma.sync.aligned.m16n8k16.row.col.f32.bf16.bf16.f32 "
        "{%0,%1,%2,%3}, {%4,%5,%6,%7}, {%8,%9}, {%0,%1,%2,%3};"
        : "+f"(c[0]), "+f"(c[1]), "+f"(c[2]), "+f"(c[3])
        : "r"(a[0]), "r"(a[1]), "r"(a[2]), "r"(a[3]), "r"(b[0]), "r"(b[1]));
}

#define LDSM4(r0, r1, r2, r3, addr) \
    asm volatile("ldmatrix.sync.aligned.m8n8.x4.shared.b16 {%0,%1,%2,%3}, [%4];" \
                 : "=r"(r0), "=r"(r1), "=r"(r2), "=r"(r3) : "r"(addr))

#define LDSM2T(r0, r1, addr) \
    asm volatile("ldmatrix.sync.aligned.m8n8.x2.trans.shared.b16 {%0,%1}, [%2];" \
                 : "=r"(r0), "=r"(r1) : "r"(addr))

#define CPA(dst, src, sz) \
    asm volatile("cp.async.ca.shared.global [%0], [%1], 16, %2;" \
                 :: "r"(dst), "l"(src), "r"(sz) : "memory")
#define CP_COMMIT() asm volatile("cp.async.commit_group;" ::: "memory")
#define CP_WAIT1()  asm volatile("cp.async.wait_group 1;" ::: "memory")
#define CP_WAIT0()  asm volatile("cp.async.wait_group 0;" ::: "memory")

__device__ __forceinline__ void pair_hilo(float a, float b, uint32_t& h, uint32_t& l) {
    __nv_bfloat162 hh = __floats2bfloat162_rn(a, b);
    float2 f = __bfloat1622float2(hh);
    __nv_bfloat162 ll = __floats2bfloat162_rn(a - f.x, b - f.y);
    h = *(uint32_t*)&hh; l = *(uint32_t*)&ll;
}
__device__ __forceinline__ void scalar_hilo(float v, bf16& h, bf16& l) {
    h = __float2bfloat16_rn(v);
    l = __float2bfloat16_rn(v - __bfloat162float(h));
}

// ============================ prep kernels ==================================
__global__ void prep_w3(const float* __restrict__ w0, const float* __restrict__ w1,
                        const float* __restrict__ w2, const float* __restrict__ w3,
                        const float* __restrict__ w4, const float* __restrict__ w5,
                        bf16* __restrict__ wh, bf16* __restrict__ wl) {
    const float* ws[6] = {w0, w1, w2, w3, w4, w5};
    int conv = blockIdx.y;
    const float* w = ws[conv];
    int t = blockIdx.x * 256 + threadIdx.x;
    int co = t >> 9, ci = t & 511;
    float v[9];
#pragma unroll
    for (int r = 0; r < 9; ++r) v[r] = w[(size_t)t * 9 + r];
#pragma unroll
    for (int r = 0; r < 9; ++r) {
        size_t o = (((size_t)conv * 9 + r) * 512 + co) * 512 + ci;
        bf16 h, l; scalar_hilo(v[r], h, l);
        wh[o] = h; wl[o] = l;
    }
}
__global__ void prep_wp(const float* __restrict__ wp1, const float* __restrict__ wp2,
                        bf16* __restrict__ wh, bf16* __restrict__ wl) {
    int pidx = blockIdx.y;
    const float* w = pidx ? wp2 : wp1;
    int idx = blockIdx.x * 256 + threadIdx.x;
    bf16 h, l; scalar_hilo(w[idx], h, l);
    size_t o = (size_t)pidx * 512 * 512 + idx;
    wh[o] = h; wl[o] = l;
}
__global__ void transpose_x(const float* __restrict__ xl, const float* __restrict__ xg,
                            bf16* __restrict__ xth, bf16* __restrict__ xtl) {
    __shared__ float tile[32][33];
    int zt = blockIdx.z, tsel = zt >> 2, n = zt & 3;
    const float* x = (tsel ? xg : xl) + (size_t)n * (CCH * HW);
    size_t ob = (size_t)tsel * NB * HW * CCH + (size_t)n * (HW * CCH);
    int hw0 = blockIdx.x * 32, c0 = blockIdx.y * 32;
    int tx = threadIdx.x, ty = threadIdx.y;
#pragma unroll
    for (int i = 0; i < 32; i += 8)
        tile[ty + i][tx] = x[(size_t)(c0 + ty + i) * HW + hw0 + tx];
    __syncthreads();
#pragma unroll
    for (int i = 0; i < 32; i += 8) {
        float v = tile[tx][ty + i];
        bf16 h, l; scalar_hilo(v, h, l);
        size_t o = ob + (size_t)(hw0 + ty + i) * CCH + c0 + tx;
        xth[o] = h; xtl[o] = l;
    }
}

// ============================ layout consts =================================
#define ROWB 80
#define MATB (128 * ROWB)             // 10240
#define ROW2 272
#define MATB2 (32 * ROW2)             // 8704
#define STG4 (4 * MATB)               // 40960
#define SM4  (2 * STG4)               // 81920
#define STGT (2 * MATB + 2 * MATB2)   // 37888
#define SMT  (2 * STGT)               // 75776

// ======================= shared mma inner phases ============================
__device__ __forceinline__ void mma_phase_nn(uint32_t st, uint32_t a_base,
                                             uint32_t b_base, float acc[4][4][4]) {
    uint32_t sAh = st, sAl = st + MATB, sBh = st + 2 * MATB, sBl = st + 3 * MATB;
#pragma unroll
    for (int kt = 0; kt < 2; ++kt) {
        uint32_t aH[4][4], aL[4][4], bH[4][2], bL[4][2];
#pragma unroll
        for (int mt = 0; mt < 4; ++mt) {
            uint32_t ad = a_base + (uint32_t)(mt * 16 * ROWB + kt * 32);
            LDSM4(aH[mt][0], aH[mt][1], aH[mt][2], aH[mt][3], sAh + ad);
            LDSM4(aL[mt][0], aL[mt][1], aL[mt][2], aL[mt][3], sAl + ad);
        }
#pragma unroll
        for (int p = 0; p < 2; ++p) {
            uint32_t bd = b_base + (uint32_t)(p * 16 * ROWB + kt * 32);
            uint32_t r0, r1, r2, r3;
            LDSM4(r0, r1, r2, r3, sBh + bd);
            bH[2 * p][0] = r0; bH[2 * p][1] = r2;
            bH[2 * p + 1][0] = r1; bH[2 * p + 1][1] = r3;
            LDSM4(r0, r1, r2, r3, sBl + bd);
            bL[2 * p][0] = r0; bL[2 * p][1] = r2;
            bL[2 * p + 1][0] = r1; bL[2 * p + 1][1] = r3;
        }
#pragma unroll
        for (int mt = 0; mt < 4; ++mt)
#pragma unroll
            for (int nt = 0; nt < 4; ++nt) {
                mma_bf16(acc[mt][nt], aH[mt], bH[nt]);
                mma_bf16(acc[mt][nt], aH[mt], bL[nt]);
                mma_bf16(acc[mt][nt], aL[mt], bH[nt]);
            }
    }
}

__device__ __forceinline__ void mma_phase_nt(uint32_t st, uint32_t a_base,
                                             uint32_t bt_base, float acc[4][4][4]) {
    uint32_t sAh = st, sAl = st + MATB;
    uint32_t sBh = st + 2 * MATB, sBl = st + 2 * MATB + MATB2;
#pragma unroll
    for (int kt = 0; kt < 2; ++kt) {
        uint32_t aH[4][4], aL[4][4], bH[4][2], bL[4][2];
#pragma unroll
        for (int mt = 0; mt < 4; ++mt) {
            uint32_t ad = a_base + (uint32_t)(mt * 16 * ROWB + kt * 32);
            LDSM4(aH[mt][0], aH[mt][1], aH[mt][2], aH[mt][3], sAh + ad);
            LDSM4(aL[mt][0], aL[mt][1], aL[mt][2], aL[mt][3], sAl + ad);
        }
#pragma unroll
        for (int nt = 0; nt < 4; ++nt) {
            uint32_t bd = bt_base + (uint32_t)(kt * 16 * ROW2 + nt * 16);
            LDSM2T(bH[nt][0], bH[nt][1], sBh + bd);
            LDSM2T(bL[nt][0], bL[nt][1], sBl + bd);
        }
#pragma unroll
        for (int mt = 0; mt < 4; ++mt)
#pragma unroll
            for (int nt = 0; nt < 4; ++nt) {
                mma_bf16(acc[mt][nt], aH[mt], bH[nt]);
                mma_bf16(acc[mt][nt], aH[mt], bL[nt]);
                mma_bf16(acc[mt][nt], aL[mt], bH[nt]);
            }
    }
}

// ================== conv 3x3: cp.async.ca 2-stage + mma =====================
// grid (8 s-tiles, 4 co-tiles, 24 conv*n); output bf16 hi/lo.
__global__ __launch_bounds__(256, 2)
void conv_mma_kernel(const bf16* __restrict__ xth, const bf16* __restrict__ xtl,
                     const bf16* __restrict__ wh, const bf16* __restrict__ wl,
                     bf16* __restrict__ qh, bf16* __restrict__ ql) {
    extern __shared__ unsigned char dsm[];
    const uint32_t sb = smem_u32(dsm);

    int tid = threadIdx.x, wid = tid >> 5, lid = tid & 31;
    int warp_m = wid >> 2, warp_n = wid & 3;
    int sp0 = blockIdx.x * 128, co0 = blockIdx.y * 128;
    int conv = blockIdx.z >> 2, n = blockIdx.z & 3;
    size_t xoffb = ((size_t)(conv < 3 ? 0 : 1) * NB + n) * (HW * CCH);
    const bf16* xh = xth + xoffb;
    const bf16* xl = xtl + xoffb;
    const bf16* wbh = wh + (size_t)conv * (9 * 512 * 512);
    const bf16* wbl = wl + (size_t)conv * (9 * 512 * 512);
    size_t ob = ((size_t)conv * NB + n) * (CCH * HW);
    bf16* oh = qh + ob;
    bf16* ol = ql + ob;

    float acc[4][4][4];
#pragma unroll
    for (int mt = 0; mt < 4; ++mt)
#pragma unroll
        for (int nt = 0; nt < 4; ++nt)
#pragma unroll
            for (int k = 0; k < 4; ++k) acc[mt][nt][k] = 0.f;

    int grp = lid >> 3, lr = lid & 7;
    uint32_t a_base = (uint32_t)((warp_m * 64 + (grp & 1) * 8 + lr) * ROWB + (grp >> 1) * 16);
    uint32_t b_base = (uint32_t)((warp_n * 32 + (grp & 1) * 8 + lr) * ROWB + (grp >> 1) * 16);

    int row = tid >> 1, half = tid & 1;
    uint32_t dstA = (uint32_t)(row * ROWB + half * 32);

    auto prefetch = [&](int ch, int st) {
        uint32_t s0b = sb + st * STG4;
        int r = ch >> 4, ci0 = (ch & 15) << 5;
        int dy = r / 3 - 1, dx = r % 3 - 1;
        size_t wof = ((size_t)r * 512 + co0 + row) * 512 + ci0 + half * 16;
        uint32_t da = s0b + dstA;
        CPA(da,             wbh + wof,     16u);
        CPA(da + 16,        wbh + wof + 8, 16u);
        CPA(da + MATB,      wbl + wof,     16u);
        CPA(da + MATB + 16, wbl + wof + 8, 16u);
        int s = sp0 + row;
        int yy = (s >> 5) + dy, xx = (s & 31) + dx;
        bool ok = ((unsigned)yy < 32u) && ((unsigned)xx < 32u);
        size_t xof = ok ? ((size_t)(yy * 32 + xx) * 512 + ci0 + half * 16) : 0;
        uint32_t sz = ok ? 16u : 0u;
        uint32_t db = s0b + 2 * MATB + dstA;
        CPA(db,             xh + xof,     sz);
        CPA(db + 16,        xh + xof + 8, sz);
        CPA(db + MATB,      xl + xof,     sz);
        CPA(db + MATB + 16, xl + xof + 8, sz);
    };

    prefetch(0, 0); CP_COMMIT();
    for (int ch = 0; ch < 144; ++ch) {
        if (ch + 1 < 144) { prefetch(ch + 1, (ch + 1) & 1); CP_COMMIT(); CP_WAIT1(); }
        else CP_WAIT0();
        __syncthreads();
        mma_phase_nn(sb + (ch & 1) * STG4, a_base, b_base, acc);
        __syncthreads();
    }

#pragma unroll
    for (int mt = 0; mt < 4; ++mt) {
        int m = co0 + warp_m * 64 + mt * 16 + (lid >> 2);
#pragma unroll
        for (int nt = 0; nt < 4; ++nt) {
            int sc = sp0 + warp_n * 32 + nt * 8 + (lid & 3) * 2;
            uint32_t h2, l2;
            pair_hilo(acc[mt][nt][0], acc[mt][nt][1], h2, l2);
            *(uint32_t*)&oh[(size_t)m * HW + sc] = h2;
            *(uint32_t*)&ol[(size_t)m * HW + sc] = l2;
            pair_hilo(acc[mt][nt][2], acc[mt][nt][3], h2, l2);
            *(uint32_t*)&oh[(size_t)(m + 8) * HW + sc] = h2;
            *(uint32_t*)&ol[(size_t)(m + 8) * HW + sc] = l2;
        }
    }
}

// ================== QK^T: cp.async.ca 2-stage + mma =========================
// grid (4 ck, 4 cq, 64): z<32 -> (q_g,k_l)->att0 ; z>=32 -> (q_l,k_g)->att1
__global__ __launch_bounds__(256, 2)
void qk_mma_kernel(const bf16* __restrict__ qkh, const bf16* __restrict__ qkl,
                   float* __restrict__ att) {
    extern __shared__ unsigned char dsm[];
    const uint32_t sb = smem_u32(dsm);
    const size_t QKV_N = (size_t)NB * CCH * HW;
    const size_t ATT_N = (size_t)NB * NHD * 512 * 512;

    int tid = threadIdx.x, wid = tid >> 5, lid = tid & 31;
    int warp_m = wid >> 2, warp_n = wid & 3;
    int z = blockIdx.z, sel = z >> 5, nh = z & 31;
    int n = nh >> 3, h = nh & 7;
    int ck0 = blockIdx.x * 128, cq0 = blockIdx.y * 128;
    size_t base = (size_t)n * (CCH * HW) + h * DHEAD;
    size_t qsel = (sel ? 1 : 4) * QKV_N, ksel = (sel ? 3 : 0) * QKV_N;
    const bf16* qh = qkh + qsel + base; const bf16* ql = qkl + qsel + base;
    const bf16* kh = qkh + ksel + base; const bf16* kl = qkl + ksel + base;

    float acc[4][4][4];
#pragma unroll
    for (int mt = 0; mt < 4; ++mt)
#pragma unroll
        for (int nt = 0; nt < 4; ++nt)
#pragma unroll
            for (int kk = 0; kk < 4; ++kk) acc[mt][nt][kk] = 0.f;

    int grp = lid >> 3, lr = lid & 7;
    uint32_t a_base = (uint32_t)((warp_m * 64 + (grp & 1) * 8 + lr) * ROWB + (grp >> 1) * 16);
    uint32_t b_base = (uint32_t)((warp_n * 32 + (grp & 1) * 8 + lr) * ROWB + (grp >> 1) * 16);

    int row = tid >> 1, half = tid & 1;
    uint32_t dstA = (uint32_t)(row * ROWB + half * 32);

    auto prefetch = [&](int ch, int st) {
        uint32_t s0b = sb + st * STG4;
        int ci0 = ch << 5;
        size_t qof = (size_t)(cq0 + row) * HW + ci0 + half * 16;
        size_t kof = (size_t)(ck0 + row) * HW + ci0 + half * 16;
        uint32_t da = s0b + dstA;
        CPA(da,             qh + qof,     16u);
        CPA(da + 16,        qh + qof + 8, 16u);
        CPA(da + MATB,      ql + qof,     16u);
        CPA(da + MATB + 16, ql + qof + 8, 16u);
        uint32_t db = s0b + 2 * MATB + dstA;
        CPA(db,             kh + kof,     16u);
        CPA(db + 16,        kh + kof + 8, 16u);
        CPA(db + MATB,      kl + kof,     16u);
        CPA(db + MATB + 16, kl + kof + 8, 16u);
    };

    prefetch(0, 0); CP_COMMIT();
    for (int ch = 0; ch < 4; ++ch) {
        if (ch + 1 < 4) { prefetch(ch + 1, (ch + 1) & 1); CP_COMMIT(); CP_WAIT1(); }
        else CP_WAIT0();
        __syncthreads();
        mma_phase_nn(sb + (ch & 1) * STG4, a_base, b_base, acc);
        __syncthreads();
    }

    const float SC = 0.08838834764831845f;   // 1/sqrt(128)
    float* ab = att + sel * ATT_N + (size_t)(n * NHD + h) * 512 * 512;
#pragma unroll
    for (int mt = 0; mt < 4; ++mt) {
        int m = cq0 + warp_m * 64 + mt * 16 + (lid >> 2);
#pragma unroll
        for (int nt = 0; nt < 4; ++nt) {
            int sc = ck0 + warp_n * 32 + nt * 8 + (lid & 3) * 2;
            *(float2*)(ab + (size_t)m * 512 + sc) =
                make_float2(acc[mt][nt][0] * SC, acc[mt][nt][1] * SC);
            *(float2*)(ab + (size_t)(m + 8) * 512 + sc) =
                make_float2(acc[mt][nt][2] * SC, acc[mt][nt][3] * SC);
        }
    }
}

// ----------------- softmax: fp32 in -> bf16 hi/lo out -----------------------
__global__ void softmax_kernel(const float* __restrict__ att,
                               bf16* __restrict__ ah, bf16* __restrict__ al) {
    int row  = blockIdx.x * 8 + (threadIdx.x >> 5);
    int lane = threadIdx.x & 31;
    const float* p = att + (size_t)row * 512;
    bf16* ph = ah + (size_t)row * 512;
    bf16* pl = al + (size_t)row * 512;
    float v[16];
    float m = -1e30f;
#pragma unroll
    for (int i = 0; i < 16; ++i) { v[i] = p[lane + i * 32]; m = fmaxf(m, v[i]); }
#pragma unroll
    for (int o = 16; o; o >>= 1) m = fmaxf(m, __shfl_xor_sync(0xffffffffu, m, o));
    float s = 0.f;
#pragma unroll
    for (int i = 0; i < 16; ++i) { v[i] = __expf(v[i] - m); s += v[i]; }
#pragma unroll
    for (int o = 16; o; o >>= 1) s += __shfl_xor_sync(0xffffffffu, s, o);
    float inv = 1.f / s;
#pragma unroll
    for (int i = 0; i < 16; ++i) {
        float val = v[i] * inv;
        bf16 hh, ll; scalar_hilo(val, hh, ll);
        ph[lane + i * 32] = hh;
        pl[lane + i * 32] = ll;
    }
}

// ================== AV: cp.async.ca 2-stage + mma (B trans) =================
// grid (4 cq, 64): y<32 -> att0 @ v_l -> y_g ; y>=32 -> att1 @ v_g -> y_l
__global__ __launch_bounds__(256)
void av_mma_kernel(const bf16* __restrict__ a_h, const bf16* __restrict__ a_l,
                   const bf16* __restrict__ qkh, const bf16* __restrict__ qkl,
                   bf16* __restrict__ y_h, bf16* __restrict__ y_l) {
    extern __shared__ unsigned char dsm[];
    const uint32_t sb = smem_u32(dsm);
    const size_t QKV_N = (size_t)NB * CCH * HW;
    const size_t ATT_N = (size_t)NB * NHD * 512 * 512;

    int tid = threadIdx.x, wid = tid >> 5, lid = tid & 31;
    int warp_m = wid >> 2, warp_n = wid & 3;
    int z = blockIdx.y, sel = z >> 5, nh = z & 31;
    int n = nh >> 3, h = nh & 7;
    int cq0 = blockIdx.x * 128;
    size_t abo = sel * ATT_N + (size_t)(n * NHD + h) * 512 * 512;
    const bf16* ah = a_h + abo; const bf16* al = a_l + abo;
    size_t vsel = (sel ? 5 : 2) * QKV_N;
    size_t vbo = (size_t)n * (CCH * HW) + h * DHEAD;
    const bf16* vh = qkh + vsel + vbo; const bf16* vl = qkl + vsel + vbo;

    float acc[4][4][4];
#pragma unroll
    for (int mt = 0; mt < 4; ++mt)
#pragma unroll
        for (int nt = 0; nt < 4; ++nt)
#pragma unroll
            for (int kk = 0; kk < 4; ++kk) acc[mt][nt][kk] = 0.f;

    int grp = lid >> 3, lr = lid & 7;
    uint32_t a_base = (uint32_t)((warp_m * 64 + (grp & 1) * 8 + lr) * ROWB + (grp >> 1) * 16);
    int l16 = lid & 15;
    uint32_t bt_base = (uint32_t)(l16 * ROW2 + warp_n * 64);

    int row = tid >> 1, half = tid & 1;
    uint32_t dstA = (uint32_t)(row * ROWB + half * 32);
    int ckr = tid >> 3, seg = tid & 7;
    uint32_t dstB = (uint32_t)(ckr * ROW2 + seg * 32);

    auto prefetch = [&](int ch, int st) {
        uint32_t s0b = sb + st * STGT;
        int ci0 = ch << 5;
        size_t aof = (size_t)(cq0 + row) * 512 + ci0 + half * 16;
        uint32_t da = s0b + dstA;
        CPA(da,             ah + aof,     16u);
        CPA(da + 16,        ah + aof + 8, 16u);
        CPA(da + MATB,      al + aof,     16u);
        CPA(da + MATB + 16, al + aof + 8, 16u);
        size_t vof = (size_t)(ci0 + ckr) * HW + seg * 16;
        uint32_t db = s0b + 2 * MATB + dstB;
        CPA(db,              vh + vof,     16u);
        CPA(db + 16,         vh + vof + 8, 16u);
        CPA(db + MATB2,      vl + vof,     16u);
        CPA(db + MATB2 + 16, vl + vof + 8, 16u);
    };

    prefetch(0, 0); CP_COMMIT();
    for (int ch = 0; ch < 16; ++ch) {
        if (ch + 1 < 16) { prefetch(ch + 1, (ch + 1) & 1); CP_COMMIT(); CP_WAIT1(); }
        else CP_WAIT0();
        __syncthreads();
        mma_phase_nt(sb + (ch & 1) * STGT, a_base, bt_base, acc);
        __syncthreads();
    }

    bf16* yh = (sel ? y_h + QKV_N : y_h) + vbo;
    bf16* yl = (sel ? y_l + QKV_N : y_l) + vbo;
#pragma unroll
    for (int mt = 0; mt < 4; ++mt) {
        int m = cq0 + warp_m * 64 + mt * 16 + (lid >> 2);
#pragma unroll
        for (int nt = 0; nt < 4; ++nt) {
            int dc = warp_n * 32 + nt * 8 + (lid & 3) * 2;
            uint32_t h2, l2;
            pair_hilo(acc[mt][nt][0], acc[mt][nt][1], h2, l2);
            *(uint32_t*)&yh[(size_t)m * HW + dc] = h2;
            *(uint32_t*)&yl[(size_t)m * HW + dc] = l2;
            pair_hilo(acc[mt][nt][2], acc[mt][nt][3], h2, l2);
            *(uint32_t*)&yh[(size_t)(m + 8) * HW + dc] = h2;
            *(uint32_t*)&yl[(size_t)(m + 8) * HW + dc] = l2;
        }
    }
}

// ========= 1x1 proj + residual: cp.async.ca 2-stage (B trans) ===============
// grid (8 s, 4 co, 8): z<4 -> Wp1 @ y_l + x_l -> out_l ; else Wp2 @ y_g + x_g
__global__ __launch_bounds__(256)
void proj_mma_kernel(const bf16* __restrict__ y_hg, const bf16* __restrict__ y_lg,
                     const bf16* __restrict__ wph, const bf16* __restrict__ wpl,
                     const float* __restrict__ x_l, const float* __restrict__ x_g,
                     const float* __restrict__ rwp, float* __restrict__ out) {
    extern __shared__ unsigned char dsm[];
    const uint32_t sb = smem_u32(dsm);
    const size_t QKV_N = (size_t)NB * CCH * HW;

    int tid = threadIdx.x, wid = tid >> 5, lid = tid & 31;
    int warp_m = wid >> 2, warp_n = wid & 3;
    int z = blockIdx.z, sel = z >> 2, n = z & 3;    // sel 0: out_l, 1: out_g
    int sp0 = blockIdx.x * 128, co0 = blockIdx.y * 128;
    // sel 0 uses y_l (stored at +QKV_N), Wp1 (offset 0), x_l
    size_t ybo = (sel ? 0 : QKV_N) + (size_t)n * (CCH * HW);
    const bf16* yh = y_hg + ybo; const bf16* yl = y_lg + ybo;
    const bf16* wh = wph + (size_t)sel * 512 * 512;
    const bf16* wl = wpl + (size_t)sel * 512 * 512;
    const float* xres = sel ? x_g : x_l;
    float* outb = out + (size_t)sel * QKV_N;

    float acc[4][4][4];
#pragma unroll
    for (int mt = 0; mt < 4; ++mt)
#pragma unroll
        for (int nt = 0; nt < 4; ++nt)
#pragma unroll
            for (int kk = 0; kk < 4; ++kk) acc[mt][nt][kk] = 0.f;

    int grp = lid >> 3, lr = lid & 7;
    uint32_t a_base = (uint32_t)((warp_m * 64 + (grp & 1) * 8 + lr) * ROWB + (grp >> 1) * 16);
    int l16 = lid & 15;
    uint32_t bt_base = (uint32_t)(l16 * ROW2 + warp_n * 64);

    int row = tid >> 1, half = tid & 1;
    uint32_t dstA = (uint32_t)(row * ROWB + half * 32);
    int cir = tid >> 3, seg = tid & 7;
    uint32_t dstB = (uint32_t)(cir * ROW2 + seg * 32);

    auto prefetch = [&](int ch, int st) {
        uint32_t s0b = sb + st * STGT;
        int ci0 = ch << 5;
        size_t wof = (size_t)(co0 + row) * 512 + ci0 + half * 16;
        uint32_t da = s0b + dstA;
        CPA(da,             wh + wof,     16u);
        CPA(da + 16,        wh + wof + 8, 16u);
        CPA(da + MATB,      wl + wof,     16u);
        CPA(da + MATB + 16, wl + wof + 8, 16u);
        size_t yof = (size_t)(ci0 + cir) * HW + sp0 + seg * 16;
        uint32_t db = s0b + 2 * MATB + dstB;
        CPA(db,              yh + yof,     16u);
        CPA(db + 16,         yh + yof + 8, 16u);
        CPA(db + MATB2,      yl + yof,     16u);
        CPA(db + MATB2 + 16, yl + yof + 8, 16u);
    };

    prefetch(0, 0); CP_COMMIT();
    for (int ch = 0; ch < 16; ++ch) {
        if (ch + 1 < 16) { prefetch(ch + 1, (ch + 1) & 1); CP_COMMIT(); CP_WAIT1(); }
        else CP_WAIT0();
        __syncthreads();
        mma_phase_nt(sb + (ch & 1) * STGT, a_base, bt_base, acc);
        __syncthreads();
    }

    float rw = *rwp;
#pragma unroll
    for (int mt = 0; mt < 4; ++mt) {
        int m = co0 + warp_m * 64 + mt * 16 + (lid >> 2);
#pragma unroll
        for (int nt = 0; nt < 4; ++nt) {
            int sc = sp0 + warp_n * 32 + nt * 8 + (lid & 3) * 2;
            size_t b0 = ((size_t)n * CCH + m) * HW + sc;
            size_t b1 = ((size_t)n * CCH + m + 8) * HW + sc;
            float2 x0 = *(const float2*)(xres + b0);
            float2 x1 = *(const float2*)(xres + b1);
            *(float2*)(outb + b0) = make_float2(x0.x + rw * acc[mt][nt][0],
                                                x0.y + rw * acc[mt][nt][1]);
            *(float2*)(outb + b1) = make_float2(x1.x + rw * acc[mt][nt][2],
                                                x1.y + rw * acc[mt][nt][3]);
        }
    }
}

// ------------------------------- launcher -----------------------------------
extern "C" void kernel_launch(void* const* d_in, const int* in_sizes, int n_in,
                              void* d_out, int out_size) {
    (void)in_sizes; (void)n_in; (void)out_size;
    const float* x_l = (const float*)d_in[0];
    const float* x_g = (const float*)d_in[1];
    const float* Wp1 = (const float*)d_in[8];
    const float* Wp2 = (const float*)d_in[9];
    const float* rw  = (const float*)d_in[10];
    float* out = (float*)d_out;

    void* p;
    cudaGetSymbolAddress(&p, g_wh);  bf16* wh  = (bf16*)p;
    cudaGetSymbolAddress(&p, g_wl);  bf16* wl  = (bf16*)p;
    cudaGetSymbolAddress(&p, g_xh);  bf16* xh  = (bf16*)p;
    cudaGetSymbolAddress(&p, g_xl);  bf16* xl  = (bf16*)p;
    cudaGetSymbolAddress(&p, g_qh);  bf16* qh  = (bf16*)p;
    cudaGetSymbolAddress(&p, g_ql);  bf16* ql  = (bf16*)p;
    cudaGetSymbolAddress(&p, g_att); float* attp = (float*)p;
    cudaGetSymbolAddress(&p, g_ah);  bf16* ath = (bf16*)p;
    cudaGetSymbolAddress(&p, g_al);  bf16* atl = (bf16*)p;
    cudaGetSymbolAddress(&p, g_yh);  bf16* yh  = (bf16*)p;
    cudaGetSymbolAddress(&p, g_yl);  bf16* yl  = (bf16*)p;
    cudaGetSymbolAddress(&p, g_wph); bf16* wph = (bf16*)p;
    cudaGetSymbolAddress(&p, g_wpl); bf16* wpl = (bf16*)p;

    cudaFuncSetAttribute(conv_mma_kernel, cudaFuncAttributeMaxDynamicSharedMemorySize, SM4);
    cudaFuncSetAttribute(qk_mma_kernel,   cudaFuncAttributeMaxDynamicSharedMemorySize, SM4);
    cudaFuncSetAttribute(av_mma_kernel,   cudaFuncAttributeMaxDynamicSharedMemorySize, SMT);
    cudaFuncSetAttribute(proj_mma_kernel, cudaFuncAttributeMaxDynamicSharedMemorySize, SMT);

    prep_w3<<<dim3(1024, 6), 256>>>(
        (const float*)d_in[2], (const float*)d_in[3], (const float*)d_in[4],
        (const float*)d_in[5], (const float*)d_in[6], (const float*)d_in[7], wh, wl);
    prep_wp<<<dim3(1024, 2), 256>>>(Wp1, Wp2, wph, wpl);
    transpose_x<<<dim3(32, 16, 8), dim3(32, 8)>>>(x_l, x_g, xh, xl);

    // buffers: 0 kl, 1 ql, 2 vl, 3 kg, 4 qg, 5 vg
    conv_mma_kernel<<<dim3(8, 4, 24), 256, SM4>>>(xh, xl, wh, wl, qh, ql);

    qk_mma_kernel<<<dim3(4, 4, 64), 256, SM4>>>(qh, ql, attp);

    softmax_kernel<<<4096, 256>>>(attp, ath, atl);

    av_mma_kernel<<<dim3(4, 64), 256, SMT>>>(ath, atl, qh, ql, yh, yl);

    proj_mma_kernel<<<dim3(8, 4, 8), 256, SMT>>>(yh, yl, wph, wpl,
                                                 x_l, x_g, rw, out);
}

// round 10
// speedup vs baseline: 2.4639x; 1.4070x over previous
#include <cuda_runtime.h>
#include <cuda_fp16.h>
#include <cstdint>

// ---------------------------------------------------------------------------
// CrossAttention on GB300 (sm_103a; plain compute_103 -> mma.sync fp16).
// All GEMMs: m16n8k16 f32.f16.f16.f32 with 2-term A-split:
//   D = Ah*B + Al*B  (A = Ah + Al exact to ~2^-22; B single fp16, err ~2^-12)
// R10: same proven cp.async.ca double-buffered structure as R9, 33% fewer
// MMAs, half the B traffic.
// ---------------------------------------------------------------------------

#define NB   4
#define CCH  512
#define HW   1024
#define NHD  8
#define DHEAD 128

typedef __half fp16;

// Scratch (no allocations -> __device__ globals)
__device__ fp16  g_wh[6][9 * 512 * 512], g_wl[6][9 * 512 * 512];   // [r][co][ci]
__device__ fp16  g_x1[2][NB * HW * CCH];                           // [n][hw][ci] single
__device__ fp16  g_qh[6][NB * CCH * HW], g_ql[6][NB * CCH * HW];   // qkv hi/lo
__device__ float g_att[2][NB * NHD * 512 * 512];                   // pre-softmax
__device__ fp16  g_ah[2][NB * NHD * 512 * 512], g_al[2][NB * NHD * 512 * 512];
__device__ fp16  g_y1[2][NB * CCH * HW];                           // y single
__device__ fp16  g_wph[2][512 * 512], g_wpl[2][512 * 512];

// ============================ helpers =======================================
__device__ __forceinline__ uint32_t smem_u32(const void* p) {
    uint32_t a;
    asm("{ .reg .u64 t; cvta.to.shared.u64 t, %1; cvt.u32.u64 %0, t; }"
        : "=r"(a) : "l"(p));
    return a;
}

__device__ __forceinline__ void mma_f16(float* c, const uint32_t* a, const uint32_t* b) {
    asm volatile(
        "mma.sync.aligned.m16n8k16.row.col.f32.f16.f16.f32 "
        "{%0,%1,%2,%3}, {%4,%5,%6,%7}, {%8,%9}, {%0,%1,%2,%3};"
        : "+f"(c[0]), "+f"(c[1]), "+f"(c[2]), "+f"(c[3])
        : "r"(a[0]), "r"(a[1]), "r"(a[2]), "r"(a[3]), "r"(b[0]), "r"(b[1]));
}

#define LDSM4(r0, r1, r2, r3, addr) \
    asm volatile("ldmatrix.sync.aligned.m8n8.x4.shared.b16 {%0,%1,%2,%3}, [%4];" \
                 : "=r"(r0), "=r"(r1), "=r"(r2), "=r"(r3) : "r"(addr))

#define LDSM2T(r0, r1, addr) \
    asm volatile("ldmatrix.sync.aligned.m8n8.x2.trans.shared.b16 {%0,%1}, [%2];" \
                 : "=r"(r0), "=r"(r1) : "r"(addr))

#define CPA(dst, src, sz) \
    asm volatile("cp.async.ca.shared.global [%0], [%1], 16, %2;" \
                 :: "r"(dst), "l"(src), "r"(sz) : "memory")
#define CP_COMMIT() asm volatile("cp.async.commit_group;" ::: "memory")
#define CP_WAIT1()  asm volatile("cp.async.wait_group 1;" ::: "memory")
#define CP_WAIT0()  asm volatile("cp.async.wait_group 0;" ::: "memory")

__device__ __forceinline__ void pair_hilo(float a, float b, uint32_t& h, uint32_t& l) {
    __half2 hh = __floats2half2_rn(a, b);
    float2 f = __half22float2(hh);
    __half2 ll = __floats2half2_rn(a - f.x, b - f.y);
    h = *(uint32_t*)&hh; l = *(uint32_t*)&ll;
}
__device__ __forceinline__ void scalar_hilo(float v, fp16& h, fp16& l) {
    h = __float2half_rn(v);
    l = __float2half_rn(v - __half2float(h));
}

// ============================ prep kernels ==================================
__global__ void prep_w3(const float* __restrict__ w0, const float* __restrict__ w1,
                        const float* __restrict__ w2, const float* __restrict__ w3,
                        const float* __restrict__ w4, const float* __restrict__ w5,
                        fp16* __restrict__ wh, fp16* __restrict__ wl) {
    const float* ws[6] = {w0, w1, w2, w3, w4, w5};
    int conv = blockIdx.y;
    const float* w = ws[conv];
    int t = blockIdx.x * 256 + threadIdx.x;
    int co = t >> 9, ci = t & 511;
    float v[9];
#pragma unroll
    for (int r = 0; r < 9; ++r) v[r] = w[(size_t)t * 9 + r];
#pragma unroll
    for (int r = 0; r < 9; ++r) {
        size_t o = (((size_t)conv * 9 + r) * 512 + co) * 512 + ci;
        fp16 h, l; scalar_hilo(v[r], h, l);
        wh[o] = h; wl[o] = l;
    }
}
__global__ void prep_wp(const float* __restrict__ wp1, const float* __restrict__ wp2,
                        fp16* __restrict__ wh, fp16* __restrict__ wl) {
    int pidx = blockIdx.y;
    const float* w = pidx ? wp2 : wp1;
    int idx = blockIdx.x * 256 + threadIdx.x;
    fp16 h, l; scalar_hilo(w[idx], h, l);
    size_t o = (size_t)pidx * 512 * 512 + idx;
    wh[o] = h; wl[o] = l;
}
// x [n][c][hw] -> xt [n][hw][c] single fp16 (B operand of conv)
__global__ void transpose_x(const float* __restrict__ xl, const float* __restrict__ xg,
                            fp16* __restrict__ xt1) {
    __shared__ float tile[32][33];
    int zt = blockIdx.z, tsel = zt >> 2, n = zt & 3;
    const float* x = (tsel ? xg : xl) + (size_t)n * (CCH * HW);
    size_t ob = (size_t)tsel * NB * HW * CCH + (size_t)n * (HW * CCH);
    int hw0 = blockIdx.x * 32, c0 = blockIdx.y * 32;
    int tx = threadIdx.x, ty = threadIdx.y;
#pragma unroll
    for (int i = 0; i < 32; i += 8)
        tile[ty + i][tx] = x[(size_t)(c0 + ty + i) * HW + hw0 + tx];
    __syncthreads();
#pragma unroll
    for (int i = 0; i < 32; i += 8)
        xt1[ob + (size_t)(hw0 + ty + i) * CCH + c0 + tx] =
            __float2half_rn(tile[tx][ty + i]);
}

// ============================ layout consts =================================
#define ROWB 80
#define MATB (128 * ROWB)             // 10240
#define ROW2 272
#define MATB2 (32 * ROW2)             // 8704
#define STG3 (3 * MATB)               // nn stage: Ah Al B     30720
#define SM3  (2 * STG3)               // 61440
#define STGN (2 * MATB + MATB2)       // nt stage: Ah Al B     29184
#define SMN  (2 * STGN)               // 58368

// ======================= shared mma inner phases ============================
__device__ __forceinline__ void mma_phase_nn(uint32_t st, uint32_t a_base,
                                             uint32_t b_base, float acc[4][4][4]) {
    uint32_t sAh = st, sAl = st + MATB, sB = st + 2 * MATB;
#pragma unroll
    for (int kt = 0; kt < 2; ++kt) {
        uint32_t aH[4][4], aL[4][4], bb[4][2];
#pragma unroll
        for (int mt = 0; mt < 4; ++mt) {
            uint32_t ad = a_base + (uint32_t)(mt * 16 * ROWB + kt * 32);
            LDSM4(aH[mt][0], aH[mt][1], aH[mt][2], aH[mt][3], sAh + ad);
            LDSM4(aL[mt][0], aL[mt][1], aL[mt][2], aL[mt][3], sAl + ad);
        }
#pragma unroll
        for (int p = 0; p < 2; ++p) {
            uint32_t bd = b_base + (uint32_t)(p * 16 * ROWB + kt * 32);
            uint32_t r0, r1, r2, r3;
            LDSM4(r0, r1, r2, r3, sB + bd);
            bb[2 * p][0] = r0; bb[2 * p][1] = r2;
            bb[2 * p + 1][0] = r1; bb[2 * p + 1][1] = r3;
        }
#pragma unroll
        for (int mt = 0; mt < 4; ++mt)
#pragma unroll
            for (int nt = 0; nt < 4; ++nt) {
                mma_f16(acc[mt][nt], aH[mt], bb[nt]);
                mma_f16(acc[mt][nt], aL[mt], bb[nt]);
            }
    }
}

__device__ __forceinline__ void mma_phase_nt(uint32_t st, uint32_t a_base,
                                             uint32_t bt_base, float acc[4][4][4]) {
    uint32_t sAh = st, sAl = st + MATB, sB = st + 2 * MATB;
#pragma unroll
    for (int kt = 0; kt < 2; ++kt) {
        uint32_t aH[4][4], aL[4][4], bb[4][2];
#pragma unroll
        for (int mt = 0; mt < 4; ++mt) {
            uint32_t ad = a_base + (uint32_t)(mt * 16 * ROWB + kt * 32);
            LDSM4(aH[mt][0], aH[mt][1], aH[mt][2], aH[mt][3], sAh + ad);
            LDSM4(aL[mt][0], aL[mt][1], aL[mt][2], aL[mt][3], sAl + ad);
        }
#pragma unroll
        for (int nt = 0; nt < 4; ++nt) {
            uint32_t bd = bt_base + (uint32_t)(kt * 16 * ROW2 + nt * 16);
            LDSM2T(bb[nt][0], bb[nt][1], sB + bd);
        }
#pragma unroll
        for (int mt = 0; mt < 4; ++mt)
#pragma unroll
            for (int nt = 0; nt < 4; ++nt) {
                mma_f16(acc[mt][nt], aH[mt], bb[nt]);
                mma_f16(acc[mt][nt], aL[mt], bb[nt]);
            }
    }
}

// ================== conv 3x3: cp.async.ca 2-stage + mma =====================
// grid (8 s-tiles, 4 co-tiles, 24 conv*n); A=w hi/lo, B=x single.
__global__ __launch_bounds__(256, 2)
void conv_mma_kernel(const fp16* __restrict__ xt1,
                     const fp16* __restrict__ wh, const fp16* __restrict__ wl,
                     fp16* __restrict__ qh, fp16* __restrict__ ql) {
    extern __shared__ unsigned char dsm[];
    const uint32_t sb = smem_u32(dsm);

    int tid = threadIdx.x, wid = tid >> 5, lid = tid & 31;
    int warp_m = wid >> 2, warp_n = wid & 3;
    int sp0 = blockIdx.x * 128, co0 = blockIdx.y * 128;
    int conv = blockIdx.z >> 2, n = blockIdx.z & 3;
    const fp16* xb = xt1 + ((size_t)(conv < 3 ? 0 : 1) * NB + n) * (HW * CCH);
    const fp16* wbh = wh + (size_t)conv * (9 * 512 * 512);
    const fp16* wbl = wl + (size_t)conv * (9 * 512 * 512);
    size_t ob = ((size_t)conv * NB + n) * (CCH * HW);
    fp16* oh = qh + ob;
    fp16* ol = ql + ob;

    float acc[4][4][4];
#pragma unroll
    for (int mt = 0; mt < 4; ++mt)
#pragma unroll
        for (int nt = 0; nt < 4; ++nt)
#pragma unroll
            for (int k = 0; k < 4; ++k) acc[mt][nt][k] = 0.f;

    int grp = lid >> 3, lr = lid & 7;
    uint32_t a_base = (uint32_t)((warp_m * 64 + (grp & 1) * 8 + lr) * ROWB + (grp >> 1) * 16);
    uint32_t b_base = (uint32_t)((warp_n * 32 + (grp & 1) * 8 + lr) * ROWB + (grp >> 1) * 16);

    int row = tid >> 1, half = tid & 1;
    uint32_t dstA = (uint32_t)(row * ROWB + half * 32);

    auto prefetch = [&](int ch, int st) {
        uint32_t s0b = sb + st * STG3;
        int r = ch >> 4, ci0 = (ch & 15) << 5;
        int dy = r / 3 - 1, dx = r % 3 - 1;
        size_t wof = ((size_t)r * 512 + co0 + row) * 512 + ci0 + half * 16;
        uint32_t da = s0b + dstA;
        CPA(da,             wbh + wof,     16u);
        CPA(da + 16,        wbh + wof + 8, 16u);
        CPA(da + MATB,      wbl + wof,     16u);
        CPA(da + MATB + 16, wbl + wof + 8, 16u);
        int s = sp0 + row;
        int yy = (s >> 5) + dy, xx = (s & 31) + dx;
        bool ok = ((unsigned)yy < 32u) && ((unsigned)xx < 32u);
        size_t xof = ok ? ((size_t)(yy * 32 + xx) * 512 + ci0 + half * 16) : 0;
        uint32_t sz = ok ? 16u : 0u;
        uint32_t db = s0b + 2 * MATB + dstA;
        CPA(db,      xb + xof,     sz);
        CPA(db + 16, xb + xof + 8, sz);
    };

    prefetch(0, 0); CP_COMMIT();
    for (int ch = 0; ch < 144; ++ch) {
        if (ch + 1 < 144) { prefetch(ch + 1, (ch + 1) & 1); CP_COMMIT(); CP_WAIT1(); }
        else CP_WAIT0();
        __syncthreads();
        mma_phase_nn(sb + (ch & 1) * STG3, a_base, b_base, acc);
        __syncthreads();
    }

#pragma unroll
    for (int mt = 0; mt < 4; ++mt) {
        int m = co0 + warp_m * 64 + mt * 16 + (lid >> 2);
#pragma unroll
        for (int nt = 0; nt < 4; ++nt) {
            int sc = sp0 + warp_n * 32 + nt * 8 + (lid & 3) * 2;
            uint32_t h2, l2;
            pair_hilo(acc[mt][nt][0], acc[mt][nt][1], h2, l2);
            *(uint32_t*)&oh[(size_t)m * HW + sc] = h2;
            *(uint32_t*)&ol[(size_t)m * HW + sc] = l2;
            pair_hilo(acc[mt][nt][2], acc[mt][nt][3], h2, l2);
            *(uint32_t*)&oh[(size_t)(m + 8) * HW + sc] = h2;
            *(uint32_t*)&ol[(size_t)(m + 8) * HW + sc] = l2;
        }
    }
}

// ================== QK^T: cp.async.ca 2-stage + mma =========================
// grid (4 ck, 4 cq, 64). A=q hi/lo, B=k single (hi buffer).
__global__ __launch_bounds__(256, 2)
void qk_mma_kernel(const fp16* __restrict__ qkh, const fp16* __restrict__ qkl,
                   float* __restrict__ att) {
    extern __shared__ unsigned char dsm[];
    const uint32_t sb = smem_u32(dsm);
    const size_t QKV_N = (size_t)NB * CCH * HW;
    const size_t ATT_N = (size_t)NB * NHD * 512 * 512;

    int tid = threadIdx.x, wid = tid >> 5, lid = tid & 31;
    int warp_m = wid >> 2, warp_n = wid & 3;
    int z = blockIdx.z, sel = z >> 5, nh = z & 31;
    int n = nh >> 3, h = nh & 7;
    int ck0 = blockIdx.x * 128, cq0 = blockIdx.y * 128;
    size_t base = (size_t)n * (CCH * HW) + h * DHEAD;
    size_t qsel = (sel ? 1 : 4) * QKV_N, ksel = (sel ? 3 : 0) * QKV_N;
    const fp16* qh = qkh + qsel + base; const fp16* ql = qkl + qsel + base;
    const fp16* kh = qkh + ksel + base;

    float acc[4][4][4];
#pragma unroll
    for (int mt = 0; mt < 4; ++mt)
#pragma unroll
        for (int nt = 0; nt < 4; ++nt)
#pragma unroll
            for (int kk = 0; kk < 4; ++kk) acc[mt][nt][kk] = 0.f;

    int grp = lid >> 3, lr = lid & 7;
    uint32_t a_base = (uint32_t)((warp_m * 64 + (grp & 1) * 8 + lr) * ROWB + (grp >> 1) * 16);
    uint32_t b_base = (uint32_t)((warp_n * 32 + (grp & 1) * 8 + lr) * ROWB + (grp >> 1) * 16);

    int row = tid >> 1, half = tid & 1;
    uint32_t dstA = (uint32_t)(row * ROWB + half * 32);

    auto prefetch = [&](int ch, int st) {
        uint32_t s0b = sb + st * STG3;
        int ci0 = ch << 5;
        size_t qof = (size_t)(cq0 + row) * HW + ci0 + half * 16;
        size_t kof = (size_t)(ck0 + row) * HW + ci0 + half * 16;
        uint32_t da = s0b + dstA;
        CPA(da,             qh + qof,     16u);
        CPA(da + 16,        qh + qof + 8, 16u);
        CPA(da + MATB,      ql + qof,     16u);
        CPA(da + MATB + 16, ql + qof + 8, 16u);
        uint32_t db = s0b + 2 * MATB + dstA;
        CPA(db,      kh + kof,     16u);
        CPA(db + 16, kh + kof + 8, 16u);
    };

    prefetch(0, 0); CP_COMMIT();
    for (int ch = 0; ch < 4; ++ch) {
        if (ch + 1 < 4) { prefetch(ch + 1, (ch + 1) & 1); CP_COMMIT(); CP_WAIT1(); }
        else CP_WAIT0();
        __syncthreads();
        mma_phase_nn(sb + (ch & 1) * STG3, a_base, b_base, acc);
        __syncthreads();
    }

    const float SC = 0.08838834764831845f;   // 1/sqrt(128)
    float* ab = att + sel * ATT_N + (size_t)(n * NHD + h) * 512 * 512;
#pragma unroll
    for (int mt = 0; mt < 4; ++mt) {
        int m = cq0 + warp_m * 64 + mt * 16 + (lid >> 2);
#pragma unroll
        for (int nt = 0; nt < 4; ++nt) {
            int sc = ck0 + warp_n * 32 + nt * 8 + (lid & 3) * 2;
            *(float2*)(ab + (size_t)m * 512 + sc) =
                make_float2(acc[mt][nt][0] * SC, acc[mt][nt][1] * SC);
            *(float2*)(ab + (size_t)(m + 8) * 512 + sc) =
                make_float2(acc[mt][nt][2] * SC, acc[mt][nt][3] * SC);
        }
    }
}

// ----------------- softmax: fp32 in -> fp16 hi/lo out -----------------------
__global__ void softmax_kernel(const float* __restrict__ att,
                               fp16* __restrict__ ah, fp16* __restrict__ al) {
    int row  = blockIdx.x * 8 + (threadIdx.x >> 5);
    int lane = threadIdx.x & 31;
    const float* p = att + (size_t)row * 512;
    fp16* ph = ah + (size_t)row * 512;
    fp16* pl = al + (size_t)row * 512;
    float v[16];
    float m = -1e30f;
#pragma unroll
    for (int i = 0; i < 16; ++i) { v[i] = p[lane + i * 32]; m = fmaxf(m, v[i]); }
#pragma unroll
    for (int o = 16; o; o >>= 1) m = fmaxf(m, __shfl_xor_sync(0xffffffffu, m, o));
    float s = 0.f;
#pragma unroll
    for (int i = 0; i < 16; ++i) { v[i] = __expf(v[i] - m); s += v[i]; }
#pragma unroll
    for (int o = 16; o; o >>= 1) s += __shfl_xor_sync(0xffffffffu, s, o);
    float inv = 1.f / s;
#pragma unroll
    for (int i = 0; i < 16; ++i) {
        float val = v[i] * inv;
        fp16 hh, ll; scalar_hilo(val, hh, ll);
        ph[lane + i * 32] = hh;
        pl[lane + i * 32] = ll;
    }
}

// ================== AV: cp.async.ca 2-stage + mma (B trans) =================
// grid (4 cq, 64). A=att hi/lo, B=v single. Output y single fp16.
__global__ __launch_bounds__(256)
void av_mma_kernel(const fp16* __restrict__ a_h, const fp16* __restrict__ a_l,
                   const fp16* __restrict__ qkh, fp16* __restrict__ y1) {
    extern __shared__ unsigned char dsm[];
    const uint32_t sb = smem_u32(dsm);
    const size_t QKV_N = (size_t)NB * CCH * HW;
    const size_t ATT_N = (size_t)NB * NHD * 512 * 512;

    int tid = threadIdx.x, wid = tid >> 5, lid = tid & 31;
    int warp_m = wid >> 2, warp_n = wid & 3;
    int z = blockIdx.y, sel = z >> 5, nh = z & 31;
    int n = nh >> 3, h = nh & 7;
    int cq0 = blockIdx.x * 128;
    size_t abo = sel * ATT_N + (size_t)(n * NHD + h) * 512 * 512;
    const fp16* ah = a_h + abo; const fp16* al = a_l + abo;
    size_t vbo = (size_t)n * (CCH * HW) + h * DHEAD;
    const fp16* vh = qkh + (sel ? 5 : 2) * QKV_N + vbo;

    float acc[4][4][4];
#pragma unroll
    for (int mt = 0; mt < 4; ++mt)
#pragma unroll
        for (int nt = 0; nt < 4; ++nt)
#pragma unroll
            for (int kk = 0; kk < 4; ++kk) acc[mt][nt][kk] = 0.f;

    int grp = lid >> 3, lr = lid & 7;
    uint32_t a_base = (uint32_t)((warp_m * 64 + (grp & 1) * 8 + lr) * ROWB + (grp >> 1) * 16);
    int l16 = lid & 15;
    uint32_t bt_base = (uint32_t)(l16 * ROW2 + warp_n * 64);

    int row = tid >> 1, half = tid & 1;
    uint32_t dstA = (uint32_t)(row * ROWB + half * 32);
    int ckr = tid >> 3, seg = tid & 7;
    uint32_t dstB = (uint32_t)(ckr * ROW2 + seg * 32);

    auto prefetch = [&](int ch, int st) {
        uint32_t s0b = sb + st * STGN;
        int ci0 = ch << 5;
        size_t aof = (size_t)(cq0 + row) * 512 + ci0 + half * 16;
        uint32_t da = s0b + dstA;
        CPA(da,             ah + aof,     16u);
        CPA(da + 16,        ah + aof + 8, 16u);
        CPA(da + MATB,      al + aof,     16u);
        CPA(da + MATB + 16, al + aof + 8, 16u);
        size_t vof = (size_t)(ci0 + ckr) * HW + seg * 16;
        uint32_t db = s0b + 2 * MATB + dstB;
        CPA(db,      vh + vof,     16u);
        CPA(db + 16, vh + vof + 8, 16u);
    };

    prefetch(0, 0); CP_COMMIT();
    for (int ch = 0; ch < 16; ++ch) {
        if (ch + 1 < 16) { prefetch(ch + 1, (ch + 1) & 1); CP_COMMIT(); CP_WAIT1(); }
        else CP_WAIT0();
        __syncthreads();
        mma_phase_nt(sb + (ch & 1) * STGN, a_base, bt_base, acc);
        __syncthreads();
    }

    fp16* yb = y1 + (sel ? QKV_N : 0) + vbo;
#pragma unroll
    for (int mt = 0; mt < 4; ++mt) {
        int m = cq0 + warp_m * 64 + mt * 16 + (lid >> 2);
#pragma unroll
        for (int nt = 0; nt < 4; ++nt) {
            int dc = warp_n * 32 + nt * 8 + (lid & 3) * 2;
            __half2 p0 = __floats2half2_rn(acc[mt][nt][0], acc[mt][nt][1]);
            __half2 p1 = __floats2half2_rn(acc[mt][nt][2], acc[mt][nt][3]);
            *(uint32_t*)&yb[(size_t)m * HW + dc] = *(uint32_t*)&p0;
            *(uint32_t*)&yb[(size_t)(m + 8) * HW + dc] = *(uint32_t*)&p1;
        }
    }
}

// ========= 1x1 proj + residual: cp.async.ca 2-stage (B trans) ===============
// grid (8 s, 4 co, 8). A=Wp hi/lo, B=y single.
__global__ __launch_bounds__(256)
void proj_mma_kernel(const fp16* __restrict__ y1,
                     const fp16* __restrict__ wph, const fp16* __restrict__ wpl,
                     const float* __restrict__ x_l, const float* __restrict__ x_g,
                     const float* __restrict__ rwp, float* __restrict__ out) {
    extern __shared__ unsigned char dsm[];
    const uint32_t sb = smem_u32(dsm);
    const size_t QKV_N = (size_t)NB * CCH * HW;

    int tid = threadIdx.x, wid = tid >> 5, lid = tid & 31;
    int warp_m = wid >> 2, warp_n = wid & 3;
    int z = blockIdx.z, sel = z >> 2, n = z & 3;    // sel 0: out_l, 1: out_g
    int sp0 = blockIdx.x * 128, co0 = blockIdx.y * 128;
    // sel 0 uses y_l (stored at +QKV_N), Wp1 (offset 0), x_l
    const fp16* yb = y1 + (sel ? 0 : QKV_N) + (size_t)n * (CCH * HW);
    const fp16* wh = wph + (size_t)sel * 512 * 512;
    const fp16* wl = wpl + (size_t)sel * 512 * 512;
    const float* xres = sel ? x_g : x_l;
    float* outb = out + (size_t)sel * QKV_N;

    float acc[4][4][4];
#pragma unroll
    for (int mt = 0; mt < 4; ++mt)
#pragma unroll
        for (int nt = 0; nt < 4; ++nt)
#pragma unroll
            for (int kk = 0; kk < 4; ++kk) acc[mt][nt][kk] = 0.f;

    int grp = lid >> 3, lr = lid & 7;
    uint32_t a_base = (uint32_t)((warp_m * 64 + (grp & 1) * 8 + lr) * ROWB + (grp >> 1) * 16);
    int l16 = lid & 15;
    uint32_t bt_base = (uint32_t)(l16 * ROW2 + warp_n * 64);

    int row = tid >> 1, half = tid & 1;
    uint32_t dstA = (uint32_t)(row * ROWB + half * 32);
    int cir = tid >> 3, seg = tid & 7;
    uint32_t dstB = (uint32_t)(cir * ROW2 + seg * 32);

    auto prefetch = [&](int ch, int st) {
        uint32_t s0b = sb + st * STGN;
        int ci0 = ch << 5;
        size_t wof = (size_t)(co0 + row) * 512 + ci0 + half * 16;
        uint32_t da = s0b + dstA;
        CPA(da,             wh + wof,     16u);
        CPA(da + 16,        wh + wof + 8, 16u);
        CPA(da + MATB,      wl + wof,     16u);
        CPA(da + MATB + 16, wl + wof + 8, 16u);
        size_t yof = (size_t)(ci0 + cir) * HW + sp0 + seg * 16;
        uint32_t db = s0b + 2 * MATB + dstB;
        CPA(db,      yb + yof,     16u);
        CPA(db + 16, yb + yof + 8, 16u);
    };

    prefetch(0, 0); CP_COMMIT();
    for (int ch = 0; ch < 16; ++ch) {
        if (ch + 1 < 16) { prefetch(ch + 1, (ch + 1) & 1); CP_COMMIT(); CP_WAIT1(); }
        else CP_WAIT0();
        __syncthreads();
        mma_phase_nt(sb + (ch & 1) * STGN, a_base, bt_base, acc);
        __syncthreads();
    }

    float rw = *rwp;
#pragma unroll
    for (int mt = 0; mt < 4; ++mt) {
        int m = co0 + warp_m * 64 + mt * 16 + (lid >> 2);
#pragma unroll
        for (int nt = 0; nt < 4; ++nt) {
            int sc = sp0 + warp_n * 32 + nt * 8 + (lid & 3) * 2;
            size_t b0 = ((size_t)n * CCH + m) * HW + sc;
            size_t b1 = ((size_t)n * CCH + m + 8) * HW + sc;
            float2 x0 = *(const float2*)(xres + b0);
            float2 x1 = *(const float2*)(xres + b1);
            *(float2*)(outb + b0) = make_float2(x0.x + rw * acc[mt][nt][0],
                                                x0.y + rw * acc[mt][nt][1]);
            *(float2*)(outb + b1) = make_float2(x1.x + rw * acc[mt][nt][2],
                                                x1.y + rw * acc[mt][nt][3]);
        }
    }
}

// ------------------------------- launcher -----------------------------------
extern "C" void kernel_launch(void* const* d_in, const int* in_sizes, int n_in,
                              void* d_out, int out_size) {
    (void)in_sizes; (void)n_in; (void)out_size;
    const float* x_l = (const float*)d_in[0];
    const float* x_g = (const float*)d_in[1];
    const float* Wp1 = (const float*)d_in[8];
    const float* Wp2 = (const float*)d_in[9];
    const float* rw  = (const float*)d_in[10];
    float* out = (float*)d_out;

    void* p;
    cudaGetSymbolAddress(&p, g_wh);  fp16* wh  = (fp16*)p;
    cudaGetSymbolAddress(&p, g_wl);  fp16* wl  = (fp16*)p;
    cudaGetSymbolAddress(&p, g_x1);  fp16* x1  = (fp16*)p;
    cudaGetSymbolAddress(&p, g_qh);  fp16* qh  = (fp16*)p;
    cudaGetSymbolAddress(&p, g_ql);  fp16* ql  = (fp16*)p;
    cudaGetSymbolAddress(&p, g_att); float* attp = (float*)p;
    cudaGetSymbolAddress(&p, g_ah);  fp16* ath = (fp16*)p;
    cudaGetSymbolAddress(&p, g_al);  fp16* atl = (fp16*)p;
    cudaGetSymbolAddress(&p, g_y1);  fp16* y1  = (fp16*)p;
    cudaGetSymbolAddress(&p, g_wph); fp16* wph = (fp16*)p;
    cudaGetSymbolAddress(&p, g_wpl); fp16* wpl = (fp16*)p;

    cudaFuncSetAttribute(conv_mma_kernel, cudaFuncAttributeMaxDynamicSharedMemorySize, SM3);
    cudaFuncSetAttribute(qk_mma_kernel,   cudaFuncAttributeMaxDynamicSharedMemorySize, SM3);
    cudaFuncSetAttribute(av_mma_kernel,   cudaFuncAttributeMaxDynamicSharedMemorySize, SMN);
    cudaFuncSetAttribute(proj_mma_kernel, cudaFuncAttributeMaxDynamicSharedMemorySize, SMN);

    prep_w3<<<dim3(1024, 6), 256>>>(
        (const float*)d_in[2], (const float*)d_in[3], (const float*)d_in[4],
        (const float*)d_in[5], (const float*)d_in[6], (const float*)d_in[7], wh, wl);
    prep_wp<<<dim3(1024, 2), 256>>>(Wp1, Wp2, wph, wpl);
    transpose_x<<<dim3(32, 16, 8), dim3(32, 8)>>>(x_l, x_g, x1);

    // buffers: 0 kl, 1 ql, 2 vl, 3 kg, 4 qg, 5 vg
    conv_mma_kernel<<<dim3(8, 4, 24), 256, SM3>>>(x1, wh, wl, qh, ql);

    qk_mma_kernel<<<dim3(4, 4, 64), 256, SM3>>>(qh, ql, attp);

    softmax_kernel<<<4096, 256>>>(attp, ath, atl);

    av_mma_kernel<<<dim3(4, 64), 256, SMN>>>(ath, atl, qh, y1);

    proj_mma_kernel<<<dim3(8, 4, 8), 256, SMN>>>(y1, wph, wpl, x_l, x_g, rw, out);
}

// round 11
// speedup vs baseline: 3.8471x; 1.5614x over previous
#include <cuda_runtime.h>
#include <cuda_fp16.h>
#include <cstdint>

// ---------------------------------------------------------------------------
// CrossAttention on GB300 (sm_103a; plain compute_103 -> mma.sync fp16).
// R11: conv = single fp16 x single fp16 (1 MMA per fragment; error ~2^-12
// per operand, measured-safe). qk/av/proj keep 2-term A-split
// (D = Ah*B + Al*B). Same proven cp.async.ca double-buffered structure.
// ---------------------------------------------------------------------------

#define NB   4
#define CCH  512
#define HW   1024
#define NHD  8
#define DHEAD 128

typedef __half fp16;

// Scratch (no allocations -> __device__ globals)
__device__ fp16  g_w1[6][9 * 512 * 512];                           // [r][co][ci] single
__device__ fp16  g_x1[2][NB * HW * CCH];                           // [n][hw][ci] single
__device__ fp16  g_qh[6][NB * CCH * HW], g_ql[6][NB * CCH * HW];   // qkv hi/lo
__device__ float g_att[2][NB * NHD * 512 * 512];                   // pre-softmax
__device__ fp16  g_ah[2][NB * NHD * 512 * 512], g_al[2][NB * NHD * 512 * 512];
__device__ fp16  g_y1[2][NB * CCH * HW];                           // y single
__device__ fp16  g_wph[2][512 * 512], g_wpl[2][512 * 512];

// ============================ helpers =======================================
__device__ __forceinline__ uint32_t smem_u32(const void* p) {
    uint32_t a;
    asm("{ .reg .u64 t; cvta.to.shared.u64 t, %1; cvt.u32.u64 %0, t; }"
        : "=r"(a) : "l"(p));
    return a;
}

__device__ __forceinline__ void mma_f16(float* c, const uint32_t* a, const uint32_t* b) {
    asm volatile(
        "mma.sync.aligned.m16n8k16.row.col.f32.f16.f16.f32 "
        "{%0,%1,%2,%3}, {%4,%5,%6,%7}, {%8,%9}, {%0,%1,%2,%3};"
        : "+f"(c[0]), "+f"(c[1]), "+f"(c[2]), "+f"(c[3])
        : "r"(a[0]), "r"(a[1]), "r"(a[2]), "r"(a[3]), "r"(b[0]), "r"(b[1]));
}

#define LDSM4(r0, r1, r2, r3, addr) \
    asm volatile("ldmatrix.sync.aligned.m8n8.x4.shared.b16 {%0,%1,%2,%3}, [%4];" \
                 : "=r"(r0), "=r"(r1), "=r"(r2), "=r"(r3) : "r"(addr))

#define LDSM2T(r0, r1, addr) \
    asm volatile("ldmatrix.sync.aligned.m8n8.x2.trans.shared.b16 {%0,%1}, [%2];" \
                 : "=r"(r0), "=r"(r1) : "r"(addr))

#define CPA(dst, src, sz) \
    asm volatile("cp.async.ca.shared.global [%0], [%1], 16, %2;" \
                 :: "r"(dst), "l"(src), "r"(sz) : "memory")
#define CP_COMMIT() asm volatile("cp.async.commit_group;" ::: "memory")
#define CP_WAIT1()  asm volatile("cp.async.wait_group 1;" ::: "memory")
#define CP_WAIT0()  asm volatile("cp.async.wait_group 0;" ::: "memory")

__device__ __forceinline__ void pair_hilo(float a, float b, uint32_t& h, uint32_t& l) {
    __half2 hh = __floats2half2_rn(a, b);
    float2 f = __half22float2(hh);
    __half2 ll = __floats2half2_rn(a - f.x, b - f.y);
    h = *(uint32_t*)&hh; l = *(uint32_t*)&ll;
}
__device__ __forceinline__ void scalar_hilo(float v, fp16& h, fp16& l) {
    h = __float2half_rn(v);
    l = __float2half_rn(v - __half2float(h));
}

// ============================ prep kernels ==================================
// w [co][ci][3][3] -> [conv][r][co][ci] single fp16
__global__ void prep_w3(const float* __restrict__ w0, const float* __restrict__ w1,
                        const float* __restrict__ w2, const float* __restrict__ w3,
                        const float* __restrict__ w4, const float* __restrict__ w5,
                        fp16* __restrict__ wo) {
    const float* ws[6] = {w0, w1, w2, w3, w4, w5};
    int conv = blockIdx.y;
    const float* w = ws[conv];
    int t = blockIdx.x * 256 + threadIdx.x;
    int co = t >> 9, ci = t & 511;
    float v[9];
#pragma unroll
    for (int r = 0; r < 9; ++r) v[r] = w[(size_t)t * 9 + r];
#pragma unroll
    for (int r = 0; r < 9; ++r)
        wo[(((size_t)conv * 9 + r) * 512 + co) * 512 + ci] = __float2half_rn(v[r]);
}
__global__ void prep_wp(const float* __restrict__ wp1, const float* __restrict__ wp2,
                        fp16* __restrict__ wh, fp16* __restrict__ wl) {
    int pidx = blockIdx.y;
    const float* w = pidx ? wp2 : wp1;
    int idx = blockIdx.x * 256 + threadIdx.x;
    fp16 h, l; scalar_hilo(w[idx], h, l);
    size_t o = (size_t)pidx * 512 * 512 + idx;
    wh[o] = h; wl[o] = l;
}
// x [n][c][hw] -> xt [n][hw][c] single fp16
__global__ void transpose_x(const float* __restrict__ xl, const float* __restrict__ xg,
                            fp16* __restrict__ xt1) {
    __shared__ float tile[32][33];
    int zt = blockIdx.z, tsel = zt >> 2, n = zt & 3;
    const float* x = (tsel ? xg : xl) + (size_t)n * (CCH * HW);
    size_t ob = (size_t)tsel * NB * HW * CCH + (size_t)n * (HW * CCH);
    int hw0 = blockIdx.x * 32, c0 = blockIdx.y * 32;
    int tx = threadIdx.x, ty = threadIdx.y;
#pragma unroll
    for (int i = 0; i < 32; i += 8)
        tile[ty + i][tx] = x[(size_t)(c0 + ty + i) * HW + hw0 + tx];
    __syncthreads();
#pragma unroll
    for (int i = 0; i < 32; i += 8)
        xt1[ob + (size_t)(hw0 + ty + i) * CCH + c0 + tx] =
            __float2half_rn(tile[tx][ty + i]);
}

// ============================ layout consts =================================
#define ROWB 80
#define MATB (128 * ROWB)             // 10240
#define ROW2 272
#define MATB2 (32 * ROW2)             // 8704
#define STG2 (2 * MATB)               // conv stage: A B       20480
#define SM2  (2 * STG2)               // 40960
#define STG3 (3 * MATB)               // qk stage: Ah Al B     30720
#define SM3  (2 * STG3)               // 61440
#define STGN (2 * MATB + MATB2)       // nt stage: Ah Al B     29184
#define SMN  (2 * STGN)               // 58368

// ======================= mma inner phases ===================================
// single-A (conv): D = A*B, 32 MMA/warp/chunk
__device__ __forceinline__ void mma_phase_nn1(uint32_t st, uint32_t a_base,
                                              uint32_t b_base, float acc[4][4][4]) {
    uint32_t sA = st, sB = st + MATB;
#pragma unroll
    for (int kt = 0; kt < 2; ++kt) {
        uint32_t aa[4][4], bb[4][2];
#pragma unroll
        for (int mt = 0; mt < 4; ++mt) {
            uint32_t ad = a_base + (uint32_t)(mt * 16 * ROWB + kt * 32);
            LDSM4(aa[mt][0], aa[mt][1], aa[mt][2], aa[mt][3], sA + ad);
        }
#pragma unroll
        for (int p = 0; p < 2; ++p) {
            uint32_t bd = b_base + (uint32_t)(p * 16 * ROWB + kt * 32);
            uint32_t r0, r1, r2, r3;
            LDSM4(r0, r1, r2, r3, sB + bd);
            bb[2 * p][0] = r0; bb[2 * p][1] = r2;
            bb[2 * p + 1][0] = r1; bb[2 * p + 1][1] = r3;
        }
#pragma unroll
        for (int mt = 0; mt < 4; ++mt)
#pragma unroll
            for (int nt = 0; nt < 4; ++nt)
                mma_f16(acc[mt][nt], aa[mt], bb[nt]);
    }
}

// 2-term A-split (qk): D = Ah*B + Al*B
__device__ __forceinline__ void mma_phase_nn2(uint32_t st, uint32_t a_base,
                                              uint32_t b_base, float acc[4][4][4]) {
    uint32_t sAh = st, sAl = st + MATB, sB = st + 2 * MATB;
#pragma unroll
    for (int kt = 0; kt < 2; ++kt) {
        uint32_t aH[4][4], aL[4][4], bb[4][2];
#pragma unroll
        for (int mt = 0; mt < 4; ++mt) {
            uint32_t ad = a_base + (uint32_t)(mt * 16 * ROWB + kt * 32);
            LDSM4(aH[mt][0], aH[mt][1], aH[mt][2], aH[mt][3], sAh + ad);
            LDSM4(aL[mt][0], aL[mt][1], aL[mt][2], aL[mt][3], sAl + ad);
        }
#pragma unroll
        for (int p = 0; p < 2; ++p) {
            uint32_t bd = b_base + (uint32_t)(p * 16 * ROWB + kt * 32);
            uint32_t r0, r1, r2, r3;
            LDSM4(r0, r1, r2, r3, sB + bd);
            bb[2 * p][0] = r0; bb[2 * p][1] = r2;
            bb[2 * p + 1][0] = r1; bb[2 * p + 1][1] = r3;
        }
#pragma unroll
        for (int mt = 0; mt < 4; ++mt)
#pragma unroll
            for (int nt = 0; nt < 4; ++nt) {
                mma_f16(acc[mt][nt], aH[mt], bb[nt]);
                mma_f16(acc[mt][nt], aL[mt], bb[nt]);
            }
    }
}

__device__ __forceinline__ void mma_phase_nt(uint32_t st, uint32_t a_base,
                                             uint32_t bt_base, float acc[4][4][4]) {
    uint32_t sAh = st, sAl = st + MATB, sB = st + 2 * MATB;
#pragma unroll
    for (int kt = 0; kt < 2; ++kt) {
        uint32_t aH[4][4], aL[4][4], bb[4][2];
#pragma unroll
        for (int mt = 0; mt < 4; ++mt) {
            uint32_t ad = a_base + (uint32_t)(mt * 16 * ROWB + kt * 32);
            LDSM4(aH[mt][0], aH[mt][1], aH[mt][2], aH[mt][3], sAh + ad);
            LDSM4(aL[mt][0], aL[mt][1], aL[mt][2], aL[mt][3], sAl + ad);
        }
#pragma unroll
        for (int nt = 0; nt < 4; ++nt) {
            uint32_t bd = bt_base + (uint32_t)(kt * 16 * ROW2 + nt * 16);
            LDSM2T(bb[nt][0], bb[nt][1], sB + bd);
        }
#pragma unroll
        for (int mt = 0; mt < 4; ++mt)
#pragma unroll
            for (int nt = 0; nt < 4; ++nt) {
                mma_f16(acc[mt][nt], aH[mt], bb[nt]);
                mma_f16(acc[mt][nt], aL[mt], bb[nt]);
            }
    }
}

// ========== conv 3x3: single x single fp16, cp.async 2-stage ================
// grid (8 s-tiles, 4 co-tiles, 24 conv*n)
__global__ __launch_bounds__(256, 2)
void conv_mma_kernel(const fp16* __restrict__ xt1, const fp16* __restrict__ w1,
                     fp16* __restrict__ qh, fp16* __restrict__ ql) {
    extern __shared__ unsigned char dsm[];
    const uint32_t sb = smem_u32(dsm);

    int tid = threadIdx.x, wid = tid >> 5, lid = tid & 31;
    int warp_m = wid >> 2, warp_n = wid & 3;
    int sp0 = blockIdx.x * 128, co0 = blockIdx.y * 128;
    int conv = blockIdx.z >> 2, n = blockIdx.z & 3;
    const fp16* xb = xt1 + ((size_t)(conv < 3 ? 0 : 1) * NB + n) * (HW * CCH);
    const fp16* wb = w1 + (size_t)conv * (9 * 512 * 512);
    size_t ob = ((size_t)conv * NB + n) * (CCH * HW);
    fp16* oh = qh + ob;
    fp16* ol = ql + ob;

    float acc[4][4][4];
#pragma unroll
    for (int mt = 0; mt < 4; ++mt)
#pragma unroll
        for (int nt = 0; nt < 4; ++nt)
#pragma unroll
            for (int k = 0; k < 4; ++k) acc[mt][nt][k] = 0.f;

    int grp = lid >> 3, lr = lid & 7;
    uint32_t a_base = (uint32_t)((warp_m * 64 + (grp & 1) * 8 + lr) * ROWB + (grp >> 1) * 16);
    uint32_t b_base = (uint32_t)((warp_n * 32 + (grp & 1) * 8 + lr) * ROWB + (grp >> 1) * 16);

    int row = tid >> 1, half = tid & 1;
    uint32_t dstA = (uint32_t)(row * ROWB + half * 32);

    auto prefetch = [&](int ch, int st) {
        uint32_t s0b = sb + st * STG2;
        int r = ch >> 4, ci0 = (ch & 15) << 5;
        int dy = r / 3 - 1, dx = r % 3 - 1;
        size_t wof = ((size_t)r * 512 + co0 + row) * 512 + ci0 + half * 16;
        uint32_t da = s0b + dstA;
        CPA(da,      wb + wof,     16u);
        CPA(da + 16, wb + wof + 8, 16u);
        int s = sp0 + row;
        int yy = (s >> 5) + dy, xx = (s & 31) + dx;
        bool ok = ((unsigned)yy < 32u) && ((unsigned)xx < 32u);
        size_t xof = ok ? ((size_t)(yy * 32 + xx) * 512 + ci0 + half * 16) : 0;
        uint32_t sz = ok ? 16u : 0u;
        uint32_t db = s0b + MATB + dstA;
        CPA(db,      xb + xof,     sz);
        CPA(db + 16, xb + xof + 8, sz);
    };

    prefetch(0, 0); CP_COMMIT();
    for (int ch = 0; ch < 144; ++ch) {
        if (ch + 1 < 144) { prefetch(ch + 1, (ch + 1) & 1); CP_COMMIT(); CP_WAIT1(); }
        else CP_WAIT0();
        __syncthreads();
        mma_phase_nn1(sb + (ch & 1) * STG2, a_base, b_base, acc);
        __syncthreads();
    }

#pragma unroll
    for (int mt = 0; mt < 4; ++mt) {
        int m = co0 + warp_m * 64 + mt * 16 + (lid >> 2);
#pragma unroll
        for (int nt = 0; nt < 4; ++nt) {
            int sc = sp0 + warp_n * 32 + nt * 8 + (lid & 3) * 2;
            uint32_t h2, l2;
            pair_hilo(acc[mt][nt][0], acc[mt][nt][1], h2, l2);
            *(uint32_t*)&oh[(size_t)m * HW + sc] = h2;
            *(uint32_t*)&ol[(size_t)m * HW + sc] = l2;
            pair_hilo(acc[mt][nt][2], acc[mt][nt][3], h2, l2);
            *(uint32_t*)&oh[(size_t)(m + 8) * HW + sc] = h2;
            *(uint32_t*)&ol[(size_t)(m + 8) * HW + sc] = l2;
        }
    }
}

// ================== QK^T: cp.async.ca 2-stage + mma =========================
// grid (4 ck, 4 cq, 64). A=q hi/lo, B=k single (hi buffer).
__global__ __launch_bounds__(256, 2)
void qk_mma_kernel(const fp16* __restrict__ qkh, const fp16* __restrict__ qkl,
                   float* __restrict__ att) {
    extern __shared__ unsigned char dsm[];
    const uint32_t sb = smem_u32(dsm);
    const size_t QKV_N = (size_t)NB * CCH * HW;
    const size_t ATT_N = (size_t)NB * NHD * 512 * 512;

    int tid = threadIdx.x, wid = tid >> 5, lid = tid & 31;
    int warp_m = wid >> 2, warp_n = wid & 3;
    int z = blockIdx.z, sel = z >> 5, nh = z & 31;
    int n = nh >> 3, h = nh & 7;
    int ck0 = blockIdx.x * 128, cq0 = blockIdx.y * 128;
    size_t base = (size_t)n * (CCH * HW) + h * DHEAD;
    size_t qsel = (sel ? 1 : 4) * QKV_N, ksel = (sel ? 3 : 0) * QKV_N;
    const fp16* qh = qkh + qsel + base; const fp16* ql = qkl + qsel + base;
    const fp16* kh = qkh + ksel + base;

    float acc[4][4][4];
#pragma unroll
    for (int mt = 0; mt < 4; ++mt)
#pragma unroll
        for (int nt = 0; nt < 4; ++nt)
#pragma unroll
            for (int kk = 0; kk < 4; ++kk) acc[mt][nt][kk] = 0.f;

    int grp = lid >> 3, lr = lid & 7;
    uint32_t a_base = (uint32_t)((warp_m * 64 + (grp & 1) * 8 + lr) * ROWB + (grp >> 1) * 16);
    uint32_t b_base = (uint32_t)((warp_n * 32 + (grp & 1) * 8 + lr) * ROWB + (grp >> 1) * 16);

    int row = tid >> 1, half = tid & 1;
    uint32_t dstA = (uint32_t)(row * ROWB + half * 32);

    auto prefetch = [&](int ch, int st) {
        uint32_t s0b = sb + st * STG3;
        int ci0 = ch << 5;
        size_t qof = (size_t)(cq0 + row) * HW + ci0 + half * 16;
        size_t kof = (size_t)(ck0 + row) * HW + ci0 + half * 16;
        uint32_t da = s0b + dstA;
        CPA(da,             qh + qof,     16u);
        CPA(da + 16,        qh + qof + 8, 16u);
        CPA(da + MATB,      ql + qof,     16u);
        CPA(da + MATB + 16, ql + qof + 8, 16u);
        uint32_t db = s0b + 2 * MATB + dstA;
        CPA(db,      kh + kof,     16u);
        CPA(db + 16, kh + kof + 8, 16u);
    };

    prefetch(0, 0); CP_COMMIT();
    for (int ch = 0; ch < 4; ++ch) {
        if (ch + 1 < 4) { prefetch(ch + 1, (ch + 1) & 1); CP_COMMIT(); CP_WAIT1(); }
        else CP_WAIT0();
        __syncthreads();
        mma_phase_nn2(sb + (ch & 1) * STG3, a_base, b_base, acc);
        __syncthreads();
    }

    const float SC = 0.08838834764831845f;   // 1/sqrt(128)
    float* ab = att + sel * ATT_N + (size_t)(n * NHD + h) * 512 * 512;
#pragma unroll
    for (int mt = 0; mt < 4; ++mt) {
        int m = cq0 + warp_m * 64 + mt * 16 + (lid >> 2);
#pragma unroll
        for (int nt = 0; nt < 4; ++nt) {
            int sc = ck0 + warp_n * 32 + nt * 8 + (lid & 3) * 2;
            *(float2*)(ab + (size_t)m * 512 + sc) =
                make_float2(acc[mt][nt][0] * SC, acc[mt][nt][1] * SC);
            *(float2*)(ab + (size_t)(m + 8) * 512 + sc) =
                make_float2(acc[mt][nt][2] * SC, acc[mt][nt][3] * SC);
        }
    }
}

// ----------------- softmax: fp32 in -> fp16 hi/lo out -----------------------
__global__ void softmax_kernel(const float* __restrict__ att,
                               fp16* __restrict__ ah, fp16* __restrict__ al) {
    int row  = blockIdx.x * 8 + (threadIdx.x >> 5);
    int lane = threadIdx.x & 31;
    const float* p = att + (size_t)row * 512;
    fp16* ph = ah + (size_t)row * 512;
    fp16* pl = al + (size_t)row * 512;
    float v[16];
    float m = -1e30f;
#pragma unroll
    for (int i = 0; i < 16; ++i) { v[i] = p[lane + i * 32]; m = fmaxf(m, v[i]); }
#pragma unroll
    for (int o = 16; o; o >>= 1) m = fmaxf(m, __shfl_xor_sync(0xffffffffu, m, o));
    float s = 0.f;
#pragma unroll
    for (int i = 0; i < 16; ++i) { v[i] = __expf(v[i] - m); s += v[i]; }
#pragma unroll
    for (int o = 16; o; o >>= 1) s += __shfl_xor_sync(0xffffffffu, s, o);
    float inv = 1.f / s;
#pragma unroll
    for (int i = 0; i < 16; ++i) {
        float val = v[i] * inv;
        fp16 hh, ll; scalar_hilo(val, hh, ll);
        ph[lane + i * 32] = hh;
        pl[lane + i * 32] = ll;
    }
}

// ================== AV: cp.async.ca 2-stage + mma (B trans) =================
// grid (4 cq, 64). A=att hi/lo, B=v single. Output y single fp16.
__global__ __launch_bounds__(256)
void av_mma_kernel(const fp16* __restrict__ a_h, const fp16* __restrict__ a_l,
                   const fp16* __restrict__ qkh, fp16* __restrict__ y1) {
    extern __shared__ unsigned char dsm[];
    const uint32_t sb = smem_u32(dsm);
    const size_t QKV_N = (size_t)NB * CCH * HW;
    const size_t ATT_N = (size_t)NB * NHD * 512 * 512;

    int tid = threadIdx.x, wid = tid >> 5, lid = tid & 31;
    int warp_m = wid >> 2, warp_n = wid & 3;
    int z = blockIdx.y, sel = z >> 5, nh = z & 31;
    int n = nh >> 3, h = nh & 7;
    int cq0 = blockIdx.x * 128;
    size_t abo = sel * ATT_N + (size_t)(n * NHD + h) * 512 * 512;
    const fp16* ah = a_h + abo; const fp16* al = a_l + abo;
    size_t vbo = (size_t)n * (CCH * HW) + h * DHEAD;
    const fp16* vh = qkh + (sel ? 5 : 2) * QKV_N + vbo;

    float acc[4][4][4];
#pragma unroll
    for (int mt = 0; mt < 4; ++mt)
#pragma unroll
        for (int nt = 0; nt < 4; ++nt)
#pragma unroll
            for (int kk = 0; kk < 4; ++kk) acc[mt][nt][kk] = 0.f;

    int grp = lid >> 3, lr = lid & 7;
    uint32_t a_base = (uint32_t)((warp_m * 64 + (grp & 1) * 8 + lr) * ROWB + (grp >> 1) * 16);
    int l16 = lid & 15;
    uint32_t bt_base = (uint32_t)(l16 * ROW2 + warp_n * 64);

    int row = tid >> 1, half = tid & 1;
    uint32_t dstA = (uint32_t)(row * ROWB + half * 32);
    int ckr = tid >> 3, seg = tid & 7;
    uint32_t dstB = (uint32_t)(ckr * ROW2 + seg * 32);

    auto prefetch = [&](int ch, int st) {
        uint32_t s0b = sb + st * STGN;
        int ci0 = ch << 5;
        size_t aof = (size_t)(cq0 + row) * 512 + ci0 + half * 16;
        uint32_t da = s0b + dstA;
        CPA(da,             ah + aof,     16u);
        CPA(da + 16,        ah + aof + 8, 16u);
        CPA(da + MATB,      al + aof,     16u);
        CPA(da + MATB + 16, al + aof + 8, 16u);
        size_t vof = (size_t)(ci0 + ckr) * HW + seg * 16;
        uint32_t db = s0b + 2 * MATB + dstB;
        CPA(db,      vh + vof,     16u);
        CPA(db + 16, vh + vof + 8, 16u);
    };

    prefetch(0, 0); CP_COMMIT();
    for (int ch = 0; ch < 16; ++ch) {
        if (ch + 1 < 16) { prefetch(ch + 1, (ch + 1) & 1); CP_COMMIT(); CP_WAIT1(); }
        else CP_WAIT0();
        __syncthreads();
        mma_phase_nt(sb + (ch & 1) * STGN, a_base, bt_base, acc);
        __syncthreads();
    }

    fp16* yb = y1 + (sel ? QKV_N : 0) + vbo;
#pragma unroll
    for (int mt = 0; mt < 4; ++mt) {
        int m = cq0 + warp_m * 64 + mt * 16 + (lid >> 2);
#pragma unroll
        for (int nt = 0; nt < 4; ++nt) {
            int dc = warp_n * 32 + nt * 8 + (lid & 3) * 2;
            __half2 p0 = __floats2half2_rn(acc[mt][nt][0], acc[mt][nt][1]);
            __half2 p1 = __floats2half2_rn(acc[mt][nt][2], acc[mt][nt][3]);
            *(uint32_t*)&yb[(size_t)m * HW + dc] = *(uint32_t*)&p0;
            *(uint32_t*)&yb[(size_t)(m + 8) * HW + dc] = *(uint32_t*)&p1;
        }
    }
}

// ========= 1x1 proj + residual: cp.async.ca 2-stage (B trans) ===============
// grid (8 s, 4 co, 8). A=Wp hi/lo, B=y single.
__global__ __launch_bounds__(256)
void proj_mma_kernel(const fp16* __restrict__ y1,
                     const fp16* __restrict__ wph, const fp16* __restrict__ wpl,
                     const float* __restrict__ x_l, const float* __restrict__ x_g,
                     const float* __restrict__ rwp, float* __restrict__ out) {
    extern __shared__ unsigned char dsm[];
    const uint32_t sb = smem_u32(dsm);
    const size_t QKV_N = (size_t)NB * CCH * HW;

    int tid = threadIdx.x, wid = tid >> 5, lid = tid & 31;
    int warp_m = wid >> 2, warp_n = wid & 3;
    int z = blockIdx.z, sel = z >> 2, n = z & 3;    // sel 0: out_l, 1: out_g
    int sp0 = blockIdx.x * 128, co0 = blockIdx.y * 128;
    const fp16* yb = y1 + (sel ? 0 : QKV_N) + (size_t)n * (CCH * HW);
    const fp16* wh = wph + (size_t)sel * 512 * 512;
    const fp16* wl = wpl + (size_t)sel * 512 * 512;
    const float* xres = sel ? x_g : x_l;
    float* outb = out + (size_t)sel * QKV_N;

    float acc[4][4][4];
#pragma unroll
    for (int mt = 0; mt < 4; ++mt)
#pragma unroll
        for (int nt = 0; nt < 4; ++nt)
#pragma unroll
            for (int kk = 0; kk < 4; ++kk) acc[mt][nt][kk] = 0.f;

    int grp = lid >> 3, lr = lid & 7;
    uint32_t a_base = (uint32_t)((warp_m * 64 + (grp & 1) * 8 + lr) * ROWB + (grp >> 1) * 16);
    int l16 = lid & 15;
    uint32_t bt_base = (uint32_t)(l16 * ROW2 + warp_n * 64);

    int row = tid >> 1, half = tid & 1;
    uint32_t dstA = (uint32_t)(row * ROWB + half * 32);
    int cir = tid >> 3, seg = tid & 7;
    uint32_t dstB = (uint32_t)(cir * ROW2 + seg * 32);

    auto prefetch = [&](int ch, int st) {
        uint32_t s0b = sb + st * STGN;
        int ci0 = ch << 5;
        size_t wof = (size_t)(co0 + row) * 512 + ci0 + half * 16;
        uint32_t da = s0b + dstA;
        CPA(da,             wh + wof,     16u);
        CPA(da + 16,        wh + wof + 8, 16u);
        CPA(da + MATB,      wl + wof,     16u);
        CPA(da + MATB + 16, wl + wof + 8, 16u);
        size_t yof = (size_t)(ci0 + cir) * HW + sp0 + seg * 16;
        uint32_t db = s0b + 2 * MATB + dstB;
        CPA(db,      yb + yof,     16u);
        CPA(db + 16, yb + yof + 8, 16u);
    };

    prefetch(0, 0); CP_COMMIT();
    for (int ch = 0; ch < 16; ++ch) {
        if (ch + 1 < 16) { prefetch(ch + 1, (ch + 1) & 1); CP_COMMIT(); CP_WAIT1(); }
        else CP_WAIT0();
        __syncthreads();
        mma_phase_nt(sb + (ch & 1) * STGN, a_base, bt_base, acc);
        __syncthreads();
    }

    float rw = *rwp;
#pragma unroll
    for (int mt = 0; mt < 4; ++mt) {
        int m = co0 + warp_m * 64 + mt * 16 + (lid >> 2);
#pragma unroll
        for (int nt = 0; nt < 4; ++nt) {
            int sc = sp0 + warp_n * 32 + nt * 8 + (lid & 3) * 2;
            size_t b0 = ((size_t)n * CCH + m) * HW + sc;
            size_t b1 = ((size_t)n * CCH + m + 8) * HW + sc;
            float2 x0 = *(const float2*)(xres + b0);
            float2 x1 = *(const float2*)(xres + b1);
            *(float2*)(outb + b0) = make_float2(x0.x + rw * acc[mt][nt][0],
                                                x0.y + rw * acc[mt][nt][1]);
            *(float2*)(outb + b1) = make_float2(x1.x + rw * acc[mt][nt][2],
                                                x1.y + rw * acc[mt][nt][3]);
        }
    }
}

// ------------------------------- launcher -----------------------------------
extern "C" void kernel_launch(void* const* d_in, const int* in_sizes, int n_in,
                              void* d_out, int out_size) {
    (void)in_sizes; (void)n_in; (void)out_size;
    const float* x_l = (const float*)d_in[0];
    const float* x_g = (const float*)d_in[1];
    const float* Wp1 = (const float*)d_in[8];
    const float* Wp2 = (const float*)d_in[9];
    const float* rw  = (const float*)d_in[10];
    float* out = (float*)d_out;

    void* p;
    cudaGetSymbolAddress(&p, g_w1);  fp16* w1  = (fp16*)p;
    cudaGetSymbolAddress(&p, g_x1);  fp16* x1  = (fp16*)p;
    cudaGetSymbolAddress(&p, g_qh);  fp16* qh  = (fp16*)p;
    cudaGetSymbolAddress(&p, g_ql);  fp16* ql  = (fp16*)p;
    cudaGetSymbolAddress(&p, g_att); float* attp = (float*)p;
    cudaGetSymbolAddress(&p, g_ah);  fp16* ath = (fp16*)p;
    cudaGetSymbolAddress(&p, g_al);  fp16* atl = (fp16*)p;
    cudaGetSymbolAddress(&p, g_y1);  fp16* y1  = (fp16*)p;
    cudaGetSymbolAddress(&p, g_wph); fp16* wph = (fp16*)p;
    cudaGetSymbolAddress(&p, g_wpl); fp16* wpl = (fp16*)p;

    cudaFuncSetAttribute(conv_mma_kernel, cudaFuncAttributeMaxDynamicSharedMemorySize, SM2);
    cudaFuncSetAttribute(qk_mma_kernel,   cudaFuncAttributeMaxDynamicSharedMemorySize, SM3);
    cudaFuncSetAttribute(av_mma_kernel,   cudaFuncAttributeMaxDynamicSharedMemorySize, SMN);
    cudaFuncSetAttribute(proj_mma_kernel, cudaFuncAttributeMaxDynamicSharedMemorySize, SMN);

    prep_w3<<<dim3(1024, 6), 256>>>(
        (const float*)d_in[2], (const float*)d_in[3], (const float*)d_in[4],
        (const float*)d_in[5], (const float*)d_in[6], (const float*)d_in[7], w1);
    prep_wp<<<dim3(1024, 2), 256>>>(Wp1, Wp2, wph, wpl);
    transpose_x<<<dim3(32, 16, 8), dim3(32, 8)>>>(x_l, x_g, x1);

    // buffers: 0 kl, 1 ql, 2 vl, 3 kg, 4 qg, 5 vg
    conv_mma_kernel<<<dim3(8, 4, 24), 256, SM2>>>(x1, w1, qh, ql);

    qk_mma_kernel<<<dim3(4, 4, 64), 256, SM3>>>(qh, ql, attp);

    softmax_kernel<<<4096, 256>>>(attp, ath, atl);

    av_mma_kernel<<<dim3(4, 64), 256, SMN>>>(ath, atl, qh, y1);

    proj_mma_kernel<<<dim3(8, 4, 8), 256, SMN>>>(y1, wph, wpl, x_l, x_g, rw, out);
}